// round 10
// baseline (speedup 1.0000x reference)
#include <cuda_runtime.h>
#include <cuda_bf16.h>
#include <cuda_fp16.h>
#include <cstdint>

// ============================================================================
// Problem constants
// ============================================================================
static constexpr int B_ROWS = 131072;
static constexpr int KC     = 512;
static constexpr int TM     = 128;
static constexpr int NTILES = B_ROWS / TM;   // 1024
static constexpr int NCTAS  = 148;           // persistent grid

static constexpr float LOG2E = 1.4426950408889634f;
static constexpr float LN2   = 0.6931471805599453f;

// ============================================================================
// SMEM layout (bytes) — tile regions 1024-aligned for SW128
// ============================================================================
static constexpr int OFF_ZSQ  = 0;        // 128 f32 (log2e-scaled)
static constexpr int OFF_CSQ  = 512;      // 512 f32 (NEGATED, log2e-scaled)
static constexpr int OFF_W    = 2560;     // 128*9 f32 (chunk-max snapshots -> weights)
static constexpr int OFF_MST  = 7168;     // 2 grp x 128 rows x 4 f32 = 4 KB
static constexpr int OFF_RED  = 11264;    // warp partials + flag + dbl scratch (1 KB)
static constexpr int OFF_ZRAW = 12288;    // raw z tile fp32, 32 KB (prefetch buffer)
static constexpr int OFF_AHI  = 45056;    // z-hi  128 x 128B = 16 KB
static constexpr int OFF_ALO  = 61440;    // 16 KB
static constexpr int OFF_BHI  = 77824;    // c-hi  512 x 128B = 64 KB (PERSISTENT)
static constexpr int OFF_BLO  = 143360;   // 64 KB (PERSISTENT)
static constexpr int SMEM_BYTES = 208896; // 204 KB
// NO e-staging: e lives in registers (hp[4][32] per thread). B is never
// overwritten -> loaded once per CTA, reused for ~7 tiles.

__device__ float g_loss_partial[NCTAS];
__device__ unsigned int g_done;   // zero-init; reset by last CTA each run

#define SWZ(o) ((o) ^ (((o) >> 3) & 0x70))

// ============================================================================
// Helpers
// ============================================================================
__device__ __forceinline__ uint32_t smem_u32(const void* p) {
    uint32_t a;
    asm("{ .reg .u64 t; cvta.to.shared.u64 t, %1; cvt.u32.u64 %0, t; }" : "=r"(a) : "l"(p));
    return a;
}

__device__ __forceinline__ float ex2f(float x) {   // bare MUFU.EX2 (log2 domain)
    float r;
    asm("ex2.approx.ftz.f32 %0, %1;" : "=f"(r) : "f"(x));
    return r;
}

__device__ __forceinline__ void ldsm4(uint32_t r[4], uint32_t addr) {
    asm volatile("ldmatrix.sync.aligned.m8n8.x4.shared.b16 {%0,%1,%2,%3}, [%4];"
                 : "=r"(r[0]), "=r"(r[1]), "=r"(r[2]), "=r"(r[3]) : "r"(addr));
}

__device__ __forceinline__ void mma16816(float* d, const uint32_t* a, uint32_t b0, uint32_t b1) {
    asm volatile("mma.sync.aligned.m16n8k16.row.col.f32.bf16.bf16.f32 "
                 "{%0,%1,%2,%3}, {%4,%5,%6,%7}, {%8,%9}, {%0,%1,%2,%3};"
                 : "+f"(d[0]), "+f"(d[1]), "+f"(d[2]), "+f"(d[3])
                 : "r"(a[0]), "r"(a[1]), "r"(a[2]), "r"(a[3]), "r"(b0), "r"(b1));
}

__device__ __forceinline__ void split2(float x, float y, uint32_t& hi, uint32_t& lo) {
    __nv_bfloat16 hx = __float2bfloat16(x), hy = __float2bfloat16(y);
    float rx = x - __bfloat162float(hx);
    float ry = y - __bfloat162float(hy);
    __nv_bfloat162 h(hx, hy);
    __nv_bfloat162 l(__float2bfloat16(rx), __float2bfloat16(ry));
    hi = *reinterpret_cast<uint32_t*>(&h);
    lo = *reinterpret_cast<uint32_t*>(&l);
}

__device__ __forceinline__ void cp_async16(uint32_t dst, const void* src) {
    asm volatile("cp.async.cg.shared.global [%0], [%1], 16;" :: "r"(dst), "l"(src));
}

// One 64-col chunk of cross' for a 32-row warp tile (3 split terms fused).
// acc[64]: [rowpair(2)][nt(8)][4].
__device__ __forceinline__ void compute_chunk(
    float acc[64], uint32_t sb, uint32_t chbase,
    uint32_t aoff0, uint32_t aoff1, uint32_t bRowL, uint32_t bK16)
{
    #pragma unroll
    for (int i = 0; i < 64; i++) acc[i] = 0.f;
    #pragma unroll
    for (int ks = 0; ks < 4; ks++) {
        uint32_t a0[4], a1[4], l0[4], l1[4];
        ldsm4(a0, sb + OFF_AHI + SWZ(aoff0 + ks * 32));
        ldsm4(a1, sb + OFF_AHI + SWZ(aoff1 + ks * 32));
        ldsm4(l0, sb + OFF_ALO + SWZ(aoff0 + ks * 32));
        ldsm4(l1, sb + OFF_ALO + SWZ(aoff1 + ks * 32));
        #pragma unroll
        for (int p = 0; p < 4; p++) {
            const uint32_t bo = (chbase + p * 16 + bRowL) * 128 + bK16 + ks * 32;
            uint32_t bh[4], bl[4];
            ldsm4(bh, sb + OFF_BHI + SWZ(bo));
            ldsm4(bl, sb + OFF_BLO + SWZ(bo));
            float* A0 = acc + (p * 2) * 4;
            float* A1 = acc + (p * 2 + 1) * 4;
            float* B0 = acc + 32 + (p * 2) * 4;
            float* B1 = acc + 32 + (p * 2 + 1) * 4;
            mma16816(A0, a0, bh[0], bh[1]); mma16816(A1, a0, bh[2], bh[3]);
            mma16816(A0, a0, bl[0], bl[1]); mma16816(A1, a0, bl[2], bl[3]);
            mma16816(A0, l0, bh[0], bh[1]); mma16816(A1, l0, bh[2], bh[3]);
            mma16816(B0, a1, bh[0], bh[1]); mma16816(B1, a1, bh[2], bh[3]);
            mma16816(B0, a1, bl[0], bl[1]); mma16816(B1, a1, bl[2], bl[3]);
            mma16816(B0, l1, bh[0], bh[1]); mma16816(B1, l1, bh[2], bh[3]);
        }
    }
}

// ============================================================================
// Persistent kernel: 148 CTAs x 256 threads (8 warps)
// warp = m32-tile (mt = wid&3) x n256 col-group (grp = wid>>2, 4 chunks of 64)
// e values stay in registers across pass1 -> merge -> pass2.
// ============================================================================
__global__ void __launch_bounds__(256, 1)
soft_kmeans_kernel(const float* __restrict__ z, const float* __restrict__ cc,
                   float* __restrict__ q_out, float* __restrict__ loss_out) {
    extern __shared__ char smem[];
    const uint32_t sb = smem_u32(smem);
    const int tid  = threadIdx.x;
    const int lane = tid & 31;
    const int wid  = tid >> 5;
    const int bid  = blockIdx.x;
    const int mt   = wid & 3;     // rows mt*32 .. mt*32+31
    const int grp  = wid >> 2;    // cols grp*256 .. grp*256+255 (chunks 4g..4g+3)

    float* zsq_s = reinterpret_cast<float*>(smem + OFF_ZSQ);
    float* csq_s = reinterpret_cast<float*>(smem + OFF_CSQ);
    float* w_s   = reinterpret_cast<float*>(smem + OFF_W);
    float* mst_s = reinterpret_cast<float*>(smem + OFF_MST);
    float* red_s = reinterpret_cast<float*>(smem + OFF_RED);
    unsigned int* flag_s = reinterpret_cast<unsigned int*>(smem + OFF_RED + 64);

    const float4* z4 = reinterpret_cast<const float4*>(z);

    // ---- prefetch first z tile ---------------------------------------------
    #pragma unroll
    for (int it = 0; it < 8; it++) {
        const int idx = it * 256 + tid;
        cp_async16(sb + OFF_ZRAW + (uint32_t)idx * 16, z4 + (size_t)bid * 2048 + idx);
    }
    asm volatile("cp.async.commit_group;" ::: "memory");

    // ---- split all 512 centers ONCE (persistent for all tiles) -------------
    {
        const float4* ct = reinterpret_cast<const float4*>(cc);
        #pragma unroll 4
        for (int it = 0; it < 32; it++) {
            const int idx = it * 256 + tid;
            const int row = idx >> 4, c4 = idx & 15;
            const float4 v = ct[idx];
            float sq = v.x * v.x + v.y * v.y + v.z * v.z + v.w * v.w;
            sq += __shfl_xor_sync(~0u, sq, 1);
            sq += __shfl_xor_sync(~0u, sq, 2);
            sq += __shfl_xor_sync(~0u, sq, 4);
            sq += __shfl_xor_sync(~0u, sq, 8);
            if ((lane & 15) == 0) csq_s[row] = -sq * LOG2E;  // ready-to-add addend
            uint2 hi, lo;
            split2(v.x, v.y, hi.x, lo.x);
            split2(v.z, v.w, hi.y, lo.y);
            const uint32_t so = SWZ((uint32_t)(row * 128 + c4 * 8));
            *reinterpret_cast<uint2*>(smem + OFF_BHI + so) = hi;
            *reinterpret_cast<uint2*>(smem + OFF_BLO + so) = lo;
        }
    }

    // ---- lane decodes ------------------------------------------------------
    const int l8 = lane & 7;
    const uint32_t aCol16 = ((lane >> 4) & 1) * 16;
    const uint32_t aRow0  = (uint32_t)(mt * 32 + ((lane >> 3) & 1) * 8 + l8);
    const uint32_t aoff0  = aRow0 * 128 + aCol16;
    const uint32_t aoff1  = (aRow0 + 16) * 128 + aCol16;
    const uint32_t bRowL  = ((lane >> 4) & 1) * 8 + l8;
    const uint32_t bK16   = ((lane >> 3) & 1) * 16;

    const int rq = lane >> 2;
    int row_j[4];
    row_j[0] = mt * 32 + rq;   row_j[1] = row_j[0] + 8;
    row_j[2] = row_j[0] + 16;  row_j[3] = row_j[0] + 24;

    float cta_loss = 0.f;

    // ======================= tile loop =====================================
    for (int tile = bid; tile < NTILES; tile += NCTAS) {
        asm volatile("cp.async.wait_group 0;" ::: "memory");

        // ---- split z tile from ZRAW (each thread reads its own slots) -----
        {
            const float SC = 2.0f * LOG2E;
            #pragma unroll
            for (int it = 0; it < 8; it++) {
                const int idx = it * 256 + tid;
                const int row = idx >> 4, c4 = idx & 15;
                const float4 v = *reinterpret_cast<const float4*>(smem + OFF_ZRAW + idx * 16);
                float sq = v.x * v.x + v.y * v.y + v.z * v.z + v.w * v.w;
                sq += __shfl_xor_sync(~0u, sq, 1);
                sq += __shfl_xor_sync(~0u, sq, 2);
                sq += __shfl_xor_sync(~0u, sq, 4);
                sq += __shfl_xor_sync(~0u, sq, 8);
                if ((lane & 15) == 0) zsq_s[row] = sq * LOG2E;   // zq' (log2 domain)
                uint2 hi, lo;
                split2(SC * v.x, SC * v.y, hi.x, lo.x);
                split2(SC * v.z, SC * v.w, hi.y, lo.y);
                const uint32_t so = SWZ((uint32_t)(row * 128 + c4 * 8));
                *reinterpret_cast<uint2*>(smem + OFF_AHI + so) = hi;
                *reinterpret_cast<uint2*>(smem + OFF_ALO + so) = lo;
            }
        }
        // kick next-tile prefetch (own ZRAW slots already consumed)
        {
            const int ntile = tile + NCTAS;
            if (ntile < NTILES) {
                #pragma unroll
                for (int it = 0; it < 8; it++) {
                    const int idx = it * 256 + tid;
                    cp_async16(sb + OFF_ZRAW + (uint32_t)idx * 16,
                               z4 + (size_t)ntile * 2048 + idx);
                }
            }
            asm volatile("cp.async.commit_group;" ::: "memory");
        }
        __syncthreads();   // sync#1: A/zsq visible (covers B on first tile)

        // ---- PASS 1: 4 chunks, online (m,s,t_u), e packed into registers ---
        float m[4], s[4], tl[4];
        #pragma unroll
        for (int j = 0; j < 4; j++) { m[j] = -1e30f; s[j] = 0.f; tl[j] = 0.f; }
        uint32_t hp[4][32];   // [chunk][j*8+nt] packed half2 e values

        #pragma unroll
        for (int ci = 0; ci < 4; ci++) {
            const uint32_t chbase = (uint32_t)(grp * 256 + ci * 64);

            float acc[64];
            compute_chunk(acc, sb, chbase, aoff0, aoff1, bRowL, bK16);

            // u = cross' + (-csq'); chunk max per row-quad
            float cm[4] = {-1e30f, -1e30f, -1e30f, -1e30f};
            #pragma unroll
            for (int nt = 0; nt < 8; nt++) {
                const float2 cs = *reinterpret_cast<const float2*>(
                    csq_s + chbase + nt * 8 + (lane & 3) * 2);
                float* A = acc + nt * 4;
                float* B = acc + 32 + nt * 4;
                A[0] += cs.x;  A[1] += cs.y;
                A[2] += cs.x;  A[3] += cs.y;
                B[0] += cs.x;  B[1] += cs.y;
                B[2] += cs.x;  B[3] += cs.y;
                cm[0] = fmaxf(cm[0], fmaxf(A[0], A[1]));
                cm[1] = fmaxf(cm[1], fmaxf(A[2], A[3]));
                cm[2] = fmaxf(cm[2], fmaxf(B[0], B[1]));
                cm[3] = fmaxf(cm[3], fmaxf(B[2], B[3]));
            }
            #pragma unroll
            for (int j = 0; j < 4; j++) {
                cm[j] = fmaxf(cm[j], __shfl_xor_sync(~0u, cm[j], 1));
                cm[j] = fmaxf(cm[j], __shfl_xor_sync(~0u, cm[j], 2));
                const float nm = fmaxf(m[j], cm[j]);
                const float f = ex2f(m[j] - nm);
                s[j] *= f; tl[j] *= f; m[j] = nm;
            }
            #pragma unroll
            for (int nt = 0; nt < 8; nt++) {
                float* A = acc + nt * 4;
                float* B = acc + 32 + nt * 4;
                const float e00 = ex2f(A[0] - m[0]), e01 = ex2f(A[1] - m[0]);
                const float e10 = ex2f(A[2] - m[1]), e11 = ex2f(A[3] - m[1]);
                const float e20 = ex2f(B[0] - m[2]), e21 = ex2f(B[1] - m[2]);
                const float e30 = ex2f(B[2] - m[3]), e31 = ex2f(B[3] - m[3]);
                s[0] += e00 + e01;  tl[0] += e00 * A[0] + e01 * A[1];   // t_u = sum e*u
                s[1] += e10 + e11;  tl[1] += e10 * A[2] + e11 * A[3];
                s[2] += e20 + e21;  tl[2] += e20 * B[0] + e21 * B[1];
                s[3] += e30 + e31;  tl[3] += e30 * B[2] + e31 * B[3];
                const __half2 h0 = __floats2half2_rn(e00, e01);
                const __half2 h1 = __floats2half2_rn(e10, e11);
                const __half2 h2 = __floats2half2_rn(e20, e21);
                const __half2 h3 = __floats2half2_rn(e30, e31);
                hp[ci][0 * 8 + nt] = *reinterpret_cast<const uint32_t*>(&h0);
                hp[ci][1 * 8 + nt] = *reinterpret_cast<const uint32_t*>(&h1);
                hp[ci][2 * 8 + nt] = *reinterpret_cast<const uint32_t*>(&h2);
                hp[ci][3 * 8 + nt] = *reinterpret_cast<const uint32_t*>(&h3);
            }
            if ((lane & 3) == 0) {
                const int ch = grp * 4 + ci;
                #pragma unroll
                for (int j = 0; j < 4; j++) w_s[row_j[j] * 9 + ch] = m[j];
            }
        }

        // ---- group-local row reductions + publish (m, s, t_u) --------------
        #pragma unroll
        for (int j = 0; j < 4; j++) {
            s[j]  += __shfl_xor_sync(~0u, s[j], 1);
            s[j]  += __shfl_xor_sync(~0u, s[j], 2);
            tl[j] += __shfl_xor_sync(~0u, tl[j], 1);
            tl[j] += __shfl_xor_sync(~0u, tl[j], 2);
        }
        if ((lane & 3) == 0) {
            #pragma unroll
            for (int j = 0; j < 4; j++) {
                float* p = mst_s + (size_t)(grp * 128 + row_j[j]) * 4;
                p[0] = m[j]; p[1] = s[j]; p[2] = tl[j];
            }
        }
        __syncthreads();   // sync#2

        // ---- merge 2 groups per row (thread = row), weights, loss ----------
        float lossr = 0.f;
        if (tid < TM) {
            const float* pa = mst_s + (size_t)tid * 4;
            const float* pb = mst_s + (size_t)(128 + tid) * 4;
            const float mA = pa[0], sA = pa[1], tA = pa[2];
            const float mB = pb[0], sB = pb[1], tB = pb[2];
            const float Mv = fmaxf(mA, mB);
            const float fa = ex2f(mA - Mv), fb = ex2f(mB - Mv);
            const float sF = sA * fa + sB * fb;
            const float tF = tA * fa + tB * fb;
            const float inv = 1.f / sF;
            lossr = (zsq_s[tid] - tF * inv) * LN2;
            #pragma unroll
            for (int c = 0; c < 8; c++)
                w_s[tid * 9 + c] = ex2f(w_s[tid * 9 + c] - Mv) * inv;
        }
        #pragma unroll
        for (int o = 16; o; o >>= 1) lossr += __shfl_xor_sync(~0u, lossr, o);
        if (wid < 4 && lane == 0) red_s[wid] = lossr;
        __syncthreads();   // sync#3: w_s + red_s ready
        if (tid == 0)
            cta_loss += red_s[0] + red_s[1] + red_s[2] + red_s[3];

        // ---- PASS 2: q stores straight from registers ----------------------
        {
            float* qt = q_out + (size_t)tile * TM * KC;
            const int c2 = (lane & 3) * 2;
            #pragma unroll
            for (int ci = 0; ci < 4; ci++) {
                const int ch = grp * 4 + ci;
                const int colb = grp * 256 + ci * 64 + c2;
                float wv[4];
                #pragma unroll
                for (int j = 0; j < 4; j++) wv[j] = w_s[row_j[j] * 9 + ch];
                #pragma unroll
                for (int nt = 0; nt < 8; nt++) {
                    #pragma unroll
                    for (int j = 0; j < 4; j++) {
                        const uint32_t u = hp[ci][j * 8 + nt];
                        const float2 e = __half22float2(*reinterpret_cast<const __half2*>(&u));
                        float2 o;
                        o.x = e.x * wv[j];
                        o.y = e.y * wv[j];
                        *reinterpret_cast<float2*>(
                            qt + (size_t)row_j[j] * KC + colb + nt * 8) = o;
                    }
                }
            }
        }
    } // tile loop

    if (tid == 0) g_loss_partial[bid] = cta_loss;

    // ---- last-CTA loss finalize (deterministic fixed-order sum) ------------
    __threadfence();
    if (tid == 0) {
        const unsigned int old = atomicAdd(&g_done, 1u);
        *flag_s = (old == (unsigned int)(NCTAS - 1)) ? 1u : 0u;
    }
    __syncthreads();
    if (*flag_s) {
        double a = (tid < NCTAS) ? (double)g_loss_partial[tid] : 0.0;
        #pragma unroll
        for (int o = 16; o; o >>= 1) a += __shfl_xor_sync(~0u, a, o);
        double* dred = reinterpret_cast<double*>(smem + OFF_RED + 128);
        if (lane == 0) dred[wid] = a;
        __syncthreads();
        if (tid == 0) {
            double t = 0.0;
            #pragma unroll
            for (int i = 0; i < 8; i++) t += dred[i];
            if (loss_out) *loss_out = (float)(t / (double)B_ROWS);
            g_done = 0;   // reset for next graph replay
        }
    }
}

// ============================================================================
// Launch
// ============================================================================
extern "C" void kernel_launch(void* const* d_in, const int* in_sizes, int n_in,
                              void* d_out, int out_size) {
    const float* z  = (const float*)d_in[0];
    const float* cc = (const float*)d_in[1];
    float* q = (float*)d_out;

    const long long q_elems = (long long)B_ROWS * KC;  // 67108864
    float* loss_out = ((long long)out_size > q_elems) ? (q + q_elems) : nullptr;

    cudaFuncSetAttribute(soft_kmeans_kernel,
                         cudaFuncAttributeMaxDynamicSharedMemorySize, SMEM_BYTES);
    soft_kmeans_kernel<<<NCTAS, 256, SMEM_BYTES>>>(z, cc, q, loss_out);
}

// round 11
// speedup vs baseline: 1.4570x; 1.4570x over previous
#include <cuda_runtime.h>
#include <cuda_bf16.h>
#include <cuda_fp16.h>
#include <cstdint>

// ============================================================================
// Problem constants
// ============================================================================
static constexpr int B_ROWS = 131072;
static constexpr int KC     = 512;
static constexpr int TM     = 128;
static constexpr int NTILES = B_ROWS / TM;   // 1024
static constexpr int NCTAS  = 148;           // persistent grid

static constexpr float LOG2E = 1.4426950408889634f;
static constexpr float LN2   = 0.6931471805599453f;

// ============================================================================
// SMEM layout (bytes) — tile regions 1024-aligned for SW128
// ============================================================================
static constexpr int OFF_ZSQ  = 0;        // 128 f32 (log2e-scaled)
static constexpr int OFF_CSQ  = 512;      // 512 f32 (NEGATED, log2e-scaled)
static constexpr int OFF_W    = 2560;     // 128*9 f32 (chunk-max snapshots -> weights)
static constexpr int OFF_MST  = 7168;     // 2 grp x 128 rows x 4 f32 = 4 KB
static constexpr int OFF_RED  = 11264;    // warp partials + flag + dbl scratch (1 KB)
static constexpr int OFF_ZRAW = 12288;    // raw z tile fp32, 32 KB (prefetch buffer)
static constexpr int OFF_AHI  = 45056;    // z-hi  128 x 128B = 16 KB
static constexpr int OFF_ALO  = 61440;    // 16 KB
static constexpr int OFF_BHI  = 77824;    // c-hi  512 x 128B = 64 KB (PERSISTENT)
static constexpr int OFF_BLO  = 143360;   // 64 KB (PERSISTENT)
static constexpr int SMEM_BYTES = 208896; // 204 KB
// NO e-staging: e lives in registers (hp[64] per thread, 2 rows x 256 cols).
// B is never overwritten -> split once per CTA, reused for ~7 tiles.

__device__ float g_loss_partial[NCTAS];
__device__ unsigned int g_done;   // zero-init; reset by last CTA each run

#define SWZ(o) ((o) ^ (((o) >> 3) & 0x70))

// ============================================================================
// Helpers
// ============================================================================
__device__ __forceinline__ uint32_t smem_u32(const void* p) {
    uint32_t a;
    asm("{ .reg .u64 t; cvta.to.shared.u64 t, %1; cvt.u32.u64 %0, t; }" : "=r"(a) : "l"(p));
    return a;
}

__device__ __forceinline__ float ex2f(float x) {   // bare MUFU.EX2 (log2 domain)
    float r;
    asm("ex2.approx.ftz.f32 %0, %1;" : "=f"(r) : "f"(x));
    return r;
}

__device__ __forceinline__ void ldsm4(uint32_t r[4], uint32_t addr) {
    asm volatile("ldmatrix.sync.aligned.m8n8.x4.shared.b16 {%0,%1,%2,%3}, [%4];"
                 : "=r"(r[0]), "=r"(r[1]), "=r"(r[2]), "=r"(r[3]) : "r"(addr));
}

__device__ __forceinline__ void mma16816(float* d, const uint32_t* a, uint32_t b0, uint32_t b1) {
    asm volatile("mma.sync.aligned.m16n8k16.row.col.f32.bf16.bf16.f32 "
                 "{%0,%1,%2,%3}, {%4,%5,%6,%7}, {%8,%9}, {%0,%1,%2,%3};"
                 : "+f"(d[0]), "+f"(d[1]), "+f"(d[2]), "+f"(d[3])
                 : "r"(a[0]), "r"(a[1]), "r"(a[2]), "r"(a[3]), "r"(b0), "r"(b1));
}

__device__ __forceinline__ void split2(float x, float y, uint32_t& hi, uint32_t& lo) {
    __nv_bfloat16 hx = __float2bfloat16(x), hy = __float2bfloat16(y);
    float rx = x - __bfloat162float(hx);
    float ry = y - __bfloat162float(hy);
    __nv_bfloat162 h(hx, hy);
    __nv_bfloat162 l(__float2bfloat16(rx), __float2bfloat16(ry));
    hi = *reinterpret_cast<uint32_t*>(&h);
    lo = *reinterpret_cast<uint32_t*>(&l);
}

__device__ __forceinline__ void cp_async16(uint32_t dst, const void* src) {
    asm volatile("cp.async.cg.shared.global [%0], [%1], 16;" :: "r"(dst), "l"(src));
}

// ============================================================================
// Persistent kernel: 148 CTAs x 512 threads (16 warps)
// warp = m16-tile (mt = wid&7) x n256 col-group (grp = wid>>3, chunks 4g..4g+3)
// e values stay in registers (hp[64]) across pass1 -> merge -> pass2.
// ============================================================================
__global__ void __launch_bounds__(512, 1)
soft_kmeans_kernel(const float* __restrict__ z, const float* __restrict__ cc,
                   float* __restrict__ q_out, float* __restrict__ loss_out) {
    extern __shared__ char smem[];
    const uint32_t sb = smem_u32(smem);
    const int tid  = threadIdx.x;
    const int lane = tid & 31;
    const int wid  = tid >> 5;
    const int bid  = blockIdx.x;
    const int mt   = wid & 7;     // rows mt*16 .. mt*16+15
    const int grp  = wid >> 3;    // cols grp*256 .. grp*256+255

    float* zsq_s = reinterpret_cast<float*>(smem + OFF_ZSQ);
    float* csq_s = reinterpret_cast<float*>(smem + OFF_CSQ);
    float* w_s   = reinterpret_cast<float*>(smem + OFF_W);
    float* mst_s = reinterpret_cast<float*>(smem + OFF_MST);
    float* red_s = reinterpret_cast<float*>(smem + OFF_RED);
    unsigned int* flag_s = reinterpret_cast<unsigned int*>(smem + OFF_RED + 64);

    const float4* z4 = reinterpret_cast<const float4*>(z);

    // ---- prefetch first z tile ---------------------------------------------
    #pragma unroll
    for (int it = 0; it < 4; it++) {
        const int idx = it * 512 + tid;
        cp_async16(sb + OFF_ZRAW + (uint32_t)idx * 16, z4 + (size_t)bid * 2048 + idx);
    }
    asm volatile("cp.async.commit_group;" ::: "memory");

    // ---- split all 512 centers ONCE (persistent for all tiles) -------------
    {
        const float4* ct = reinterpret_cast<const float4*>(cc);
        #pragma unroll 4
        for (int it = 0; it < 16; it++) {
            const int idx = it * 512 + tid;
            const int row = idx >> 4, c4 = idx & 15;
            const float4 v = ct[idx];
            float sq = v.x * v.x + v.y * v.y + v.z * v.z + v.w * v.w;
            sq += __shfl_xor_sync(~0u, sq, 1);
            sq += __shfl_xor_sync(~0u, sq, 2);
            sq += __shfl_xor_sync(~0u, sq, 4);
            sq += __shfl_xor_sync(~0u, sq, 8);
            if ((lane & 15) == 0) csq_s[row] = -sq * LOG2E;  // ready-to-add addend
            uint2 hi, lo;
            split2(v.x, v.y, hi.x, lo.x);
            split2(v.z, v.w, hi.y, lo.y);
            const uint32_t so = SWZ((uint32_t)(row * 128 + c4 * 8));
            *reinterpret_cast<uint2*>(smem + OFF_BHI + so) = hi;
            *reinterpret_cast<uint2*>(smem + OFF_BLO + so) = lo;
        }
    }

    // ---- lane decodes (m16 tile) -------------------------------------------
    const uint32_t aoff = (uint32_t)(mt * 16 + ((lane >> 3) & 1) * 8 + (lane & 7)) * 128
                        + ((lane >> 4) & 1) * 16;
    const uint32_t bRowL = ((lane >> 4) & 1) * 8 + (lane & 7);
    const uint32_t bK16  = ((lane >> 3) & 1) * 16;

    const int r0 = mt * 16 + (lane >> 2);
    const int r1 = r0 + 8;

    float cta_loss = 0.f;

    // ======================= tile loop =====================================
    for (int tile = bid; tile < NTILES; tile += NCTAS) {
        asm volatile("cp.async.wait_group 0;" ::: "memory");

        // ---- split z tile from ZRAW (each thread reads its own slots) -----
        {
            const float SC = 2.0f * LOG2E;
            #pragma unroll
            for (int it = 0; it < 4; it++) {
                const int idx = it * 512 + tid;
                const int row = idx >> 4, c4 = idx & 15;
                const float4 v = *reinterpret_cast<const float4*>(smem + OFF_ZRAW + idx * 16);
                float sq = v.x * v.x + v.y * v.y + v.z * v.z + v.w * v.w;
                sq += __shfl_xor_sync(~0u, sq, 1);
                sq += __shfl_xor_sync(~0u, sq, 2);
                sq += __shfl_xor_sync(~0u, sq, 4);
                sq += __shfl_xor_sync(~0u, sq, 8);
                if ((lane & 15) == 0) zsq_s[row] = sq * LOG2E;   // zq' (log2 domain)
                uint2 hi, lo;
                split2(SC * v.x, SC * v.y, hi.x, lo.x);
                split2(SC * v.z, SC * v.w, hi.y, lo.y);
                const uint32_t so = SWZ((uint32_t)(row * 128 + c4 * 8));
                *reinterpret_cast<uint2*>(smem + OFF_AHI + so) = hi;
                *reinterpret_cast<uint2*>(smem + OFF_ALO + so) = lo;
            }
        }
        // kick next-tile prefetch (own ZRAW slots already consumed)
        {
            const int ntile = tile + NCTAS;
            if (ntile < NTILES) {
                #pragma unroll
                for (int it = 0; it < 4; it++) {
                    const int idx = it * 512 + tid;
                    cp_async16(sb + OFF_ZRAW + (uint32_t)idx * 16,
                               z4 + (size_t)ntile * 2048 + idx);
                }
            }
            asm volatile("cp.async.commit_group;" ::: "memory");
        }
        __syncthreads();   // sync#1: A/zsq visible (covers B on first tile)

        // ---- PASS 1: 4 chunks of 64 cols; online (m,s,t_u); e -> hp regs ---
        float m0 = -1e30f, s0 = 0.f, t0 = 0.f;
        float m1 = -1e30f, s1 = 0.f, t1 = 0.f;
        uint32_t hp[64];   // [ci*16 + {0..7}=r0-pairs, {8..15}=r1-pairs]

        #pragma unroll
        for (int ci = 0; ci < 4; ci++) {
            const uint32_t chbase = (uint32_t)(grp * 256 + ci * 64);

            float acc[32];   // [p(4)][sub(2)][4]
            #pragma unroll
            for (int i = 0; i < 32; i++) acc[i] = 0.f;

            #pragma unroll
            for (int ks = 0; ks < 4; ks++) {
                uint32_t ah[4], al[4];
                ldsm4(ah, sb + OFF_AHI + SWZ(aoff + ks * 32));
                ldsm4(al, sb + OFF_ALO + SWZ(aoff + ks * 32));
                #pragma unroll
                for (int p = 0; p < 4; p++) {
                    const uint32_t bo = (chbase + p * 16 + bRowL) * 128 + bK16 + ks * 32;
                    uint32_t bh[4], bl[4];
                    ldsm4(bh, sb + OFF_BHI + SWZ(bo));
                    ldsm4(bl, sb + OFF_BLO + SWZ(bo));
                    float* A0 = acc + p * 8;
                    float* A1 = acc + p * 8 + 4;
                    mma16816(A0, ah, bh[0], bh[1]); mma16816(A1, ah, bh[2], bh[3]);
                    mma16816(A0, ah, bl[0], bl[1]); mma16816(A1, ah, bl[2], bl[3]);
                    mma16816(A0, al, bh[0], bh[1]); mma16816(A1, al, bh[2], bh[3]);
                }
            }

            // u = cross' + (-csq'); chunk max per row
            float cm0 = -1e30f, cm1 = -1e30f;
            #pragma unroll
            for (int nt = 0; nt < 8; nt++) {
                const float2 cs = *reinterpret_cast<const float2*>(
                    csq_s + chbase + nt * 8 + (lane & 3) * 2);
                float* A = acc + nt * 4;
                A[0] += cs.x;  A[1] += cs.y;   // r0
                A[2] += cs.x;  A[3] += cs.y;   // r1
                cm0 = fmaxf(cm0, fmaxf(A[0], A[1]));
                cm1 = fmaxf(cm1, fmaxf(A[2], A[3]));
            }
            cm0 = fmaxf(cm0, __shfl_xor_sync(~0u, cm0, 1));
            cm0 = fmaxf(cm0, __shfl_xor_sync(~0u, cm0, 2));
            cm1 = fmaxf(cm1, __shfl_xor_sync(~0u, cm1, 1));
            cm1 = fmaxf(cm1, __shfl_xor_sync(~0u, cm1, 2));
            const float nm0 = fmaxf(m0, cm0), nm1 = fmaxf(m1, cm1);
            const float f0 = ex2f(m0 - nm0), f1 = ex2f(m1 - nm1);
            s0 *= f0; t0 *= f0; m0 = nm0;
            s1 *= f1; t1 *= f1; m1 = nm1;

            #pragma unroll
            for (int nt = 0; nt < 8; nt++) {
                float* A = acc + nt * 4;
                const float e00 = ex2f(A[0] - m0), e01 = ex2f(A[1] - m0);
                const float e10 = ex2f(A[2] - m1), e11 = ex2f(A[3] - m1);
                s0 += e00 + e01;  t0 += e00 * A[0] + e01 * A[1];   // t_u = sum e*u
                s1 += e10 + e11;  t1 += e10 * A[2] + e11 * A[3];
                const __half2 h0 = __floats2half2_rn(e00, e01);
                const __half2 h1 = __floats2half2_rn(e10, e11);
                hp[ci * 16 + nt]     = *reinterpret_cast<const uint32_t*>(&h0);
                hp[ci * 16 + 8 + nt] = *reinterpret_cast<const uint32_t*>(&h1);
            }
            if ((lane & 3) == 0) {
                const int ch = grp * 4 + ci;
                w_s[r0 * 9 + ch] = m0;   // running-max snapshot for this chunk
                w_s[r1 * 9 + ch] = m1;
            }
        }

        // ---- group-local row reductions + publish (m, s, t_u) --------------
        s0 += __shfl_xor_sync(~0u, s0, 1);  s0 += __shfl_xor_sync(~0u, s0, 2);
        t0 += __shfl_xor_sync(~0u, t0, 1);  t0 += __shfl_xor_sync(~0u, t0, 2);
        s1 += __shfl_xor_sync(~0u, s1, 1);  s1 += __shfl_xor_sync(~0u, s1, 2);
        t1 += __shfl_xor_sync(~0u, t1, 1);  t1 += __shfl_xor_sync(~0u, t1, 2);
        if ((lane & 3) == 0) {
            float* p0 = mst_s + (size_t)(grp * 128 + r0) * 4;
            float* p1 = mst_s + (size_t)(grp * 128 + r1) * 4;
            p0[0] = m0; p0[1] = s0; p0[2] = t0;
            p1[0] = m1; p1[1] = s1; p1[2] = t1;
        }
        __syncthreads();   // sync#2

        // ---- merge 2 groups per row (thread = row), weights, loss ----------
        float lossr = 0.f;
        if (tid < TM) {
            const float* pa = mst_s + (size_t)tid * 4;
            const float* pb = mst_s + (size_t)(128 + tid) * 4;
            const float mA = pa[0], sA = pa[1], tA = pa[2];
            const float mB = pb[0], sB = pb[1], tB = pb[2];
            const float Mv = fmaxf(mA, mB);
            const float fa = ex2f(mA - Mv), fb = ex2f(mB - Mv);
            const float sF = sA * fa + sB * fb;
            const float tF = tA * fa + tB * fb;
            const float inv = 1.f / sF;
            lossr = (zsq_s[tid] - tF * inv) * LN2;
            #pragma unroll
            for (int c = 0; c < 8; c++)
                w_s[tid * 9 + c] = ex2f(w_s[tid * 9 + c] - Mv) * inv;
        }
        #pragma unroll
        for (int o = 16; o; o >>= 1) lossr += __shfl_xor_sync(~0u, lossr, o);
        if (wid < 4 && lane == 0) red_s[wid] = lossr;
        __syncthreads();   // sync#3: w_s + red_s ready
        if (tid == 0)
            cta_loss += red_s[0] + red_s[1] + red_s[2] + red_s[3];

        // ---- PASS 2: q stores straight from registers ----------------------
        {
            float* qt = q_out + (size_t)tile * TM * KC;
            const int c2 = (lane & 3) * 2;
            #pragma unroll
            for (int ci = 0; ci < 4; ci++) {
                const int ch = grp * 4 + ci;
                const int colb = grp * 256 + ci * 64 + c2;
                const float w0 = w_s[r0 * 9 + ch];
                const float w1 = w_s[r1 * 9 + ch];
                #pragma unroll
                for (int nt = 0; nt < 8; nt++) {
                    const uint32_t u0 = hp[ci * 16 + nt];
                    const uint32_t u1 = hp[ci * 16 + 8 + nt];
                    const float2 e0 = __half22float2(*reinterpret_cast<const __half2*>(&u0));
                    const float2 e1 = __half22float2(*reinterpret_cast<const __half2*>(&u1));
                    float2 o;
                    o.x = e0.x * w0;  o.y = e0.y * w0;
                    *reinterpret_cast<float2*>(qt + (size_t)r0 * KC + colb + nt * 8) = o;
                    o.x = e1.x * w1;  o.y = e1.y * w1;
                    *reinterpret_cast<float2*>(qt + (size_t)r1 * KC + colb + nt * 8) = o;
                }
            }
        }
    } // tile loop

    if (tid == 0) g_loss_partial[bid] = cta_loss;

    // ---- last-CTA loss finalize (deterministic fixed-order sum) ------------
    __threadfence();
    if (tid == 0) {
        const unsigned int old = atomicAdd(&g_done, 1u);
        *flag_s = (old == (unsigned int)(NCTAS - 1)) ? 1u : 0u;
    }
    __syncthreads();
    if (*flag_s) {
        double a = (tid < NCTAS) ? (double)g_loss_partial[tid] : 0.0;
        #pragma unroll
        for (int o = 16; o; o >>= 1) a += __shfl_xor_sync(~0u, a, o);
        double* dred = reinterpret_cast<double*>(smem + OFF_RED + 128);
        if (lane == 0) dred[wid] = a;
        __syncthreads();
        if (tid == 0) {
            double t = 0.0;
            #pragma unroll
            for (int i = 0; i < 16; i++) t += dred[i];
            if (loss_out) *loss_out = (float)(t / (double)B_ROWS);
            g_done = 0;   // reset for next graph replay
        }
    }
}

// ============================================================================
// Launch
// ============================================================================
extern "C" void kernel_launch(void* const* d_in, const int* in_sizes, int n_in,
                              void* d_out, int out_size) {
    const float* z  = (const float*)d_in[0];
    const float* cc = (const float*)d_in[1];
    float* q = (float*)d_out;

    const long long q_elems = (long long)B_ROWS * KC;  // 67108864
    float* loss_out = ((long long)out_size > q_elems) ? (q + q_elems) : nullptr;

    cudaFuncSetAttribute(soft_kmeans_kernel,
                         cudaFuncAttributeMaxDynamicSharedMemorySize, SMEM_BYTES);
    soft_kmeans_kernel<<<NCTAS, 512, SMEM_BYTES>>>(z, cc, q, loss_out);
}

// round 12
// speedup vs baseline: 1.4642x; 1.0050x over previous
#include <cuda_runtime.h>
#include <cuda_bf16.h>
#include <cuda_fp16.h>
#include <cstdint>

// ============================================================================
// Problem constants
// ============================================================================
static constexpr int B_ROWS = 131072;
static constexpr int KC     = 512;
static constexpr int TM     = 128;
static constexpr int NTILES = B_ROWS / TM;   // 1024
static constexpr int NCTAS  = 148;           // persistent grid

static constexpr float LOG2E = 1.4426950408889634f;
static constexpr float LN2   = 0.6931471805599453f;

// ============================================================================
// SMEM layout (bytes) — tile regions 1024-aligned for SW128
// ============================================================================
static constexpr int OFF_ZSQ  = 0;        // 128 f32 (log2e-scaled)
static constexpr int OFF_CSQ  = 512;      // 512 f32 (NEGATED, log2e-scaled)
static constexpr int OFF_W    = 2560;     // 128*9 f32 (chunk-max snapshots -> weights)
static constexpr int OFF_MST  = 7168;     // 4 grp x 128 rows x 4 f32 = 8 KB
static constexpr int OFF_RED  = 15360;    // warp partials + flag + dbl scratch (1 KB)
static constexpr int OFF_AHI  = 16384;    // z-hi 128x128B = 16 KB; [AHI,ALO) doubles
static constexpr int OFF_ALO  = 32768;    //   as the 32 KB raw-z cp.async landing zone
static constexpr int OFF_ESTG = 49152;    // e-stage: chunk0 rows r2/r3, 32 KB
static constexpr int OFF_BHI  = 81920;    // c-hi  512 x 128B = 64 KB (PERSISTENT)
static constexpr int OFF_BLO  = 147456;   // 64 KB (PERSISTENT)
static constexpr int SMEM_BYTES = 212992; // 208 KB

__device__ float g_loss_partial[NCTAS];
__device__ unsigned int g_done;   // zero-init; reset by last CTA each run

#define SWZ(o) ((o) ^ (((o) >> 3) & 0x70))

// ============================================================================
// Helpers
// ============================================================================
__device__ __forceinline__ uint32_t smem_u32(const void* p) {
    uint32_t a;
    asm("{ .reg .u64 t; cvta.to.shared.u64 t, %1; cvt.u32.u64 %0, t; }" : "=r"(a) : "l"(p));
    return a;
}

__device__ __forceinline__ float ex2f(float x) {   // bare MUFU.EX2 (log2 domain)
    float r;
    asm("ex2.approx.ftz.f32 %0, %1;" : "=f"(r) : "f"(x));
    return r;
}

__device__ __forceinline__ void ldsm4(uint32_t r[4], uint32_t addr) {
    asm volatile("ldmatrix.sync.aligned.m8n8.x4.shared.b16 {%0,%1,%2,%3}, [%4];"
                 : "=r"(r[0]), "=r"(r[1]), "=r"(r[2]), "=r"(r[3]) : "r"(addr));
}

__device__ __forceinline__ void mma16816(float* d, const uint32_t* a, uint32_t b0, uint32_t b1) {
    asm volatile("mma.sync.aligned.m16n8k16.row.col.f32.bf16.bf16.f32 "
                 "{%0,%1,%2,%3}, {%4,%5,%6,%7}, {%8,%9}, {%0,%1,%2,%3};"
                 : "+f"(d[0]), "+f"(d[1]), "+f"(d[2]), "+f"(d[3])
                 : "r"(a[0]), "r"(a[1]), "r"(a[2]), "r"(a[3]), "r"(b0), "r"(b1));
}

__device__ __forceinline__ void split2(float x, float y, uint32_t& hi, uint32_t& lo) {
    __nv_bfloat16 hx = __float2bfloat16(x), hy = __float2bfloat16(y);
    float rx = x - __bfloat162float(hx);
    float ry = y - __bfloat162float(hy);
    __nv_bfloat162 h(hx, hy);
    __nv_bfloat162 l(__float2bfloat16(rx), __float2bfloat16(ry));
    hi = *reinterpret_cast<uint32_t*>(&h);
    lo = *reinterpret_cast<uint32_t*>(&l);
}

__device__ __forceinline__ void cp_async16(uint32_t dst, const void* src) {
    asm volatile("cp.async.cg.shared.global [%0], [%1], 16;" :: "r"(dst), "l"(src));
}

__device__ __forceinline__ void sts32(uint32_t addr, uint32_t v) {
    asm volatile("st.shared.b32 [%0], %1;" :: "r"(addr), "r"(v) : "memory");
}
__device__ __forceinline__ uint32_t lds32(uint32_t addr) {
    uint32_t v;
    asm volatile("ld.shared.b32 %0, [%1];" : "=r"(v) : "r"(addr));
    return v;
}

// One 64-col chunk of cross' for an m32 warp tile (3 split terms fused).
// acc[64]: [0..31] rows r0/r1 (m-tile A), [32..63] rows r2/r3 (m-tile B).
__device__ __forceinline__ void compute_chunk(
    float acc[64], uint32_t sb, uint32_t chbase,
    uint32_t aoff0, uint32_t aoff1, uint32_t bRowL, uint32_t bK16)
{
    #pragma unroll
    for (int i = 0; i < 64; i++) acc[i] = 0.f;
    #pragma unroll
    for (int ks = 0; ks < 4; ks++) {
        uint32_t a0[4], a1[4], l0[4], l1[4];
        ldsm4(a0, sb + OFF_AHI + SWZ(aoff0 + ks * 32));
        ldsm4(a1, sb + OFF_AHI + SWZ(aoff1 + ks * 32));
        ldsm4(l0, sb + OFF_ALO + SWZ(aoff0 + ks * 32));
        ldsm4(l1, sb + OFF_ALO + SWZ(aoff1 + ks * 32));
        #pragma unroll
        for (int p = 0; p < 4; p++) {
            const uint32_t bo = (chbase + p * 16 + bRowL) * 128 + bK16 + ks * 32;
            uint32_t bh[4], bl[4];
            ldsm4(bh, sb + OFF_BHI + SWZ(bo));
            ldsm4(bl, sb + OFF_BLO + SWZ(bo));
            float* A0 = acc + (p * 2) * 4;
            float* A1 = acc + (p * 2 + 1) * 4;
            float* B0 = acc + 32 + (p * 2) * 4;
            float* B1 = acc + 32 + (p * 2 + 1) * 4;
            mma16816(A0, a0, bh[0], bh[1]); mma16816(A1, a0, bh[2], bh[3]);
            mma16816(A0, a0, bl[0], bl[1]); mma16816(A1, a0, bl[2], bl[3]);
            mma16816(A0, l0, bh[0], bh[1]); mma16816(A1, l0, bh[2], bh[3]);
            mma16816(B0, a1, bh[0], bh[1]); mma16816(B1, a1, bh[2], bh[3]);
            mma16816(B0, a1, bl[0], bl[1]); mma16816(B1, a1, bl[2], bl[3]);
            mma16816(B0, l1, bh[0], bh[1]); mma16816(B1, l1, bh[2], bh[3]);
        }
    }
}

// ============================================================================
// Persistent kernel: 148 CTAs x 512 threads (16 warps)
// warp = m32-tile (mt = wid&3) x n128 col-group (grp = wid>>2, chunks 2g,2g+1)
// e: chunk0 r0/r1 + chunk1 all rows in regs (hp[48]); chunk0 r2/r3 in SMEM.
// ============================================================================
__global__ void __launch_bounds__(512, 1)
soft_kmeans_kernel(const float* __restrict__ z, const float* __restrict__ cc,
                   float* __restrict__ q_out, float* __restrict__ loss_out) {
    extern __shared__ char smem[];
    const uint32_t sb = smem_u32(smem);
    const int tid  = threadIdx.x;
    const int lane = tid & 31;
    const int wid  = tid >> 5;
    const int bid  = blockIdx.x;
    const int mt   = wid & 3;     // rows mt*32 .. mt*32+31
    const int grp  = wid >> 2;    // cols grp*128 .. grp*128+127

    float* zsq_s = reinterpret_cast<float*>(smem + OFF_ZSQ);
    float* csq_s = reinterpret_cast<float*>(smem + OFF_CSQ);
    float* w_s   = reinterpret_cast<float*>(smem + OFF_W);
    float* mst_s = reinterpret_cast<float*>(smem + OFF_MST);
    float* red_s = reinterpret_cast<float*>(smem + OFF_RED);
    unsigned int* flag_s = reinterpret_cast<unsigned int*>(smem + OFF_RED + 64);

    const float4* z4 = reinterpret_cast<const float4*>(z);

    // ---- prefetch first z tile into the A-region landing zone -------------
    #pragma unroll
    for (int it = 0; it < 4; it++) {
        const int idx = it * 512 + tid;
        cp_async16(sb + OFF_AHI + (uint32_t)idx * 16, z4 + (size_t)bid * 2048 + idx);
    }
    asm volatile("cp.async.commit_group;" ::: "memory");

    // ---- split all 512 centers ONCE (persistent for all tiles) -------------
    {
        const float4* ct = reinterpret_cast<const float4*>(cc);
        #pragma unroll 4
        for (int it = 0; it < 16; it++) {
            const int idx = it * 512 + tid;
            const int row = idx >> 4, c4 = idx & 15;
            const float4 v = ct[idx];
            float sq = v.x * v.x + v.y * v.y + v.z * v.z + v.w * v.w;
            sq += __shfl_xor_sync(~0u, sq, 1);
            sq += __shfl_xor_sync(~0u, sq, 2);
            sq += __shfl_xor_sync(~0u, sq, 4);
            sq += __shfl_xor_sync(~0u, sq, 8);
            if ((lane & 15) == 0) csq_s[row] = -sq * LOG2E;  // ready-to-add addend
            uint2 hi, lo;
            split2(v.x, v.y, hi.x, lo.x);
            split2(v.z, v.w, hi.y, lo.y);
            const uint32_t so = SWZ((uint32_t)(row * 128 + c4 * 8));
            *reinterpret_cast<uint2*>(smem + OFF_BHI + so) = hi;
            *reinterpret_cast<uint2*>(smem + OFF_BLO + so) = lo;
        }
    }

    // ---- lane decodes (m32 tile) -------------------------------------------
    const uint32_t aCol16 = ((lane >> 4) & 1) * 16;
    const uint32_t aRow0  = (uint32_t)(mt * 32 + ((lane >> 3) & 1) * 8 + (lane & 7));
    const uint32_t aoff0  = aRow0 * 128 + aCol16;
    const uint32_t aoff1  = (aRow0 + 16) * 128 + aCol16;
    const uint32_t bRowL  = ((lane >> 4) & 1) * 8 + (lane & 7);
    const uint32_t bK16   = ((lane >> 3) & 1) * 16;

    const int r0 = mt * 32 + (lane >> 2);   // r1=r0+8, r2=r0+16, r3=r0+24
    const uint32_t estg = sb + OFF_ESTG + (uint32_t)tid * 4;  // slot stride 2048

    float cta_loss = 0.f;

    // ======================= tile loop =====================================
    for (int tile = bid; tile < NTILES; tile += NCTAS) {
        asm volatile("cp.async.wait_group 0;" ::: "memory");

        // ---- in-place split: read own raw-z slots to regs, barrier, write --
        float4 v[4];
        #pragma unroll
        for (int it = 0; it < 4; it++) {
            const int idx = it * 512 + tid;
            v[it] = *reinterpret_cast<const float4*>(smem + OFF_AHI + idx * 16);
        }
        __syncthreads();   // syncA: all raw reads done; safe to overwrite
        {
            const float SC = 2.0f * LOG2E;
            #pragma unroll
            for (int it = 0; it < 4; it++) {
                const int idx = it * 512 + tid;
                const int row = idx >> 4, c4 = idx & 15;
                float sq = v[it].x * v[it].x + v[it].y * v[it].y
                         + v[it].z * v[it].z + v[it].w * v[it].w;
                sq += __shfl_xor_sync(~0u, sq, 1);
                sq += __shfl_xor_sync(~0u, sq, 2);
                sq += __shfl_xor_sync(~0u, sq, 4);
                sq += __shfl_xor_sync(~0u, sq, 8);
                if ((lane & 15) == 0) zsq_s[row] = sq * LOG2E;   // zq' (log2)
                uint2 hi, lo;
                split2(SC * v[it].x, SC * v[it].y, hi.x, lo.x);
                split2(SC * v[it].z, SC * v[it].w, hi.y, lo.y);
                const uint32_t so = SWZ((uint32_t)(row * 128 + c4 * 8));
                *reinterpret_cast<uint2*>(smem + OFF_AHI + so) = hi;
                *reinterpret_cast<uint2*>(smem + OFF_ALO + so) = lo;
            }
        }
        __syncthreads();   // syncB: A/zsq visible (covers B on first tile)

        // ---- PASS 1: 2 chunks of 64 cols; 4 row streams; e -> hp/SMEM ------
        float m0 = -1e30f, s0 = 0.f, t0 = 0.f;
        float m1 = -1e30f, s1 = 0.f, t1 = 0.f;
        float m2 = -1e30f, s2 = 0.f, t2 = 0.f;
        float m3 = -1e30f, s3 = 0.f, t3 = 0.f;
        uint32_t hp[48];

        #pragma unroll
        for (int ci = 0; ci < 2; ci++) {
            const uint32_t chbase = (uint32_t)(grp * 128 + ci * 64);

            float acc[64];
            compute_chunk(acc, sb, chbase, aoff0, aoff1, bRowL, bK16);

            // u = cross' + (-csq'); chunk max per row stream
            float cm0 = -1e30f, cm1 = -1e30f, cm2 = -1e30f, cm3 = -1e30f;
            #pragma unroll
            for (int nt = 0; nt < 8; nt++) {
                const float2 cs = *reinterpret_cast<const float2*>(
                    csq_s + chbase + nt * 8 + (lane & 3) * 2);
                float* A = acc + nt * 4;
                float* B = acc + 32 + nt * 4;
                A[0] += cs.x;  A[1] += cs.y;   // r0
                A[2] += cs.x;  A[3] += cs.y;   // r1
                B[0] += cs.x;  B[1] += cs.y;   // r2
                B[2] += cs.x;  B[3] += cs.y;   // r3
                cm0 = fmaxf(cm0, fmaxf(A[0], A[1]));
                cm1 = fmaxf(cm1, fmaxf(A[2], A[3]));
                cm2 = fmaxf(cm2, fmaxf(B[0], B[1]));
                cm3 = fmaxf(cm3, fmaxf(B[2], B[3]));
            }
            cm0 = fmaxf(cm0, __shfl_xor_sync(~0u, cm0, 1));
            cm0 = fmaxf(cm0, __shfl_xor_sync(~0u, cm0, 2));
            cm1 = fmaxf(cm1, __shfl_xor_sync(~0u, cm1, 1));
            cm1 = fmaxf(cm1, __shfl_xor_sync(~0u, cm1, 2));
            cm2 = fmaxf(cm2, __shfl_xor_sync(~0u, cm2, 1));
            cm2 = fmaxf(cm2, __shfl_xor_sync(~0u, cm2, 2));
            cm3 = fmaxf(cm3, __shfl_xor_sync(~0u, cm3, 1));
            cm3 = fmaxf(cm3, __shfl_xor_sync(~0u, cm3, 2));
            {
                const float nm0 = fmaxf(m0, cm0), f0 = ex2f(m0 - nm0);
                const float nm1 = fmaxf(m1, cm1), f1 = ex2f(m1 - nm1);
                const float nm2 = fmaxf(m2, cm2), f2 = ex2f(m2 - nm2);
                const float nm3 = fmaxf(m3, cm3), f3 = ex2f(m3 - nm3);
                s0 *= f0; t0 *= f0; m0 = nm0;
                s1 *= f1; t1 *= f1; m1 = nm1;
                s2 *= f2; t2 *= f2; m2 = nm2;
                s3 *= f3; t3 *= f3; m3 = nm3;
            }

            #pragma unroll
            for (int nt = 0; nt < 8; nt++) {
                float* A = acc + nt * 4;
                float* B = acc + 32 + nt * 4;
                const float e00 = ex2f(A[0] - m0), e01 = ex2f(A[1] - m0);
                const float e10 = ex2f(A[2] - m1), e11 = ex2f(A[3] - m1);
                const float e20 = ex2f(B[0] - m2), e21 = ex2f(B[1] - m2);
                const float e30 = ex2f(B[2] - m3), e31 = ex2f(B[3] - m3);
                s0 += e00 + e01;  t0 += e00 * A[0] + e01 * A[1];   // t_u = sum e*u
                s1 += e10 + e11;  t1 += e10 * A[2] + e11 * A[3];
                s2 += e20 + e21;  t2 += e20 * B[0] + e21 * B[1];
                s3 += e30 + e31;  t3 += e30 * B[2] + e31 * B[3];
                const __half2 h0 = __floats2half2_rn(e00, e01);
                const __half2 h1 = __floats2half2_rn(e10, e11);
                const __half2 h2 = __floats2half2_rn(e20, e21);
                const __half2 h3 = __floats2half2_rn(e30, e31);
                if (ci == 0) {
                    hp[nt]     = *reinterpret_cast<const uint32_t*>(&h0);
                    hp[8 + nt] = *reinterpret_cast<const uint32_t*>(&h1);
                    sts32(estg + (uint32_t)((nt * 2) * 2048),
                          *reinterpret_cast<const uint32_t*>(&h2));
                    sts32(estg + (uint32_t)((nt * 2 + 1) * 2048),
                          *reinterpret_cast<const uint32_t*>(&h3));
                } else {
                    hp[16 + nt] = *reinterpret_cast<const uint32_t*>(&h0);
                    hp[24 + nt] = *reinterpret_cast<const uint32_t*>(&h1);
                    hp[32 + nt] = *reinterpret_cast<const uint32_t*>(&h2);
                    hp[40 + nt] = *reinterpret_cast<const uint32_t*>(&h3);
                }
            }
            if ((lane & 3) == 0) {
                const int ch = grp * 2 + ci;
                w_s[r0 * 9 + ch]        = m0;
                w_s[(r0 + 8) * 9 + ch]  = m1;
                w_s[(r0 + 16) * 9 + ch] = m2;
                w_s[(r0 + 24) * 9 + ch] = m3;
            }
        }

        // ---- group-local row reductions + publish (m, s, t_u) --------------
        s0 += __shfl_xor_sync(~0u, s0, 1);  s0 += __shfl_xor_sync(~0u, s0, 2);
        t0 += __shfl_xor_sync(~0u, t0, 1);  t0 += __shfl_xor_sync(~0u, t0, 2);
        s1 += __shfl_xor_sync(~0u, s1, 1);  s1 += __shfl_xor_sync(~0u, s1, 2);
        t1 += __shfl_xor_sync(~0u, t1, 1);  t1 += __shfl_xor_sync(~0u, t1, 2);
        s2 += __shfl_xor_sync(~0u, s2, 1);  s2 += __shfl_xor_sync(~0u, s2, 2);
        t2 += __shfl_xor_sync(~0u, t2, 1);  t2 += __shfl_xor_sync(~0u, t2, 2);
        s3 += __shfl_xor_sync(~0u, s3, 1);  s3 += __shfl_xor_sync(~0u, s3, 2);
        t3 += __shfl_xor_sync(~0u, t3, 1);  t3 += __shfl_xor_sync(~0u, t3, 2);
        if ((lane & 3) == 0) {
            float* p0 = mst_s + (size_t)(grp * 128 + r0) * 4;
            p0[0] = m0; p0[1] = s0; p0[2] = t0;
            float* p1 = mst_s + (size_t)(grp * 128 + r0 + 8) * 4;
            p1[0] = m1; p1[1] = s1; p1[2] = t1;
            float* p2 = mst_s + (size_t)(grp * 128 + r0 + 16) * 4;
            p2[0] = m2; p2[1] = s2; p2[2] = t2;
            float* p3 = mst_s + (size_t)(grp * 128 + r0 + 24) * 4;
            p3[0] = m3; p3[1] = s3; p3[2] = t3;
        }
        __syncthreads();   // sync2: mst published; A region now dead

        // ---- prefetch next z tile into A landing (overlaps merge+pass2) ----
        {
            const int ntile = tile + NCTAS;
            if (ntile < NTILES) {
                #pragma unroll
                for (int it = 0; it < 4; it++) {
                    const int idx = it * 512 + tid;
                    cp_async16(sb + OFF_AHI + (uint32_t)idx * 16,
                               z4 + (size_t)ntile * 2048 + idx);
                }
            }
            asm volatile("cp.async.commit_group;" ::: "memory");
        }

        // ---- merge 4 groups per row (thread = row), weights, loss ----------
        float lossr = 0.f;
        if (tid < TM) {
            float Mv = -1e30f;
            float mg[4], sg[4], tg[4];
            #pragma unroll
            for (int g = 0; g < 4; g++) {
                const float* p = mst_s + (size_t)(g * 128 + tid) * 4;
                mg[g] = p[0]; sg[g] = p[1]; tg[g] = p[2];
                Mv = fmaxf(Mv, mg[g]);
            }
            float sF = 0.f, tF = 0.f;
            #pragma unroll
            for (int g = 0; g < 4; g++) {
                const float f = ex2f(mg[g] - Mv);
                sF += sg[g] * f; tF += tg[g] * f;
            }
            const float inv = 1.f / sF;
            lossr = (zsq_s[tid] - tF * inv) * LN2;
            #pragma unroll
            for (int c = 0; c < 8; c++)
                w_s[tid * 9 + c] = ex2f(w_s[tid * 9 + c] - Mv) * inv;
        }
        #pragma unroll
        for (int o = 16; o; o >>= 1) lossr += __shfl_xor_sync(~0u, lossr, o);
        if (wid < 4 && lane == 0) red_s[wid] = lossr;
        __syncthreads();   // sync3: w_s + red_s ready
        if (tid == 0)
            cta_loss += red_s[0] + red_s[1] + red_s[2] + red_s[3];

        // ---- PASS 2: q stores from registers + staged SMEM -----------------
        {
            float* qt = q_out + (size_t)tile * TM * KC;
            const int c2 = (lane & 3) * 2;
            #pragma unroll
            for (int ci = 0; ci < 2; ci++) {
                const int ch = grp * 2 + ci;
                const int colb = grp * 128 + ci * 64 + c2;
                const float w0 = w_s[r0 * 9 + ch];
                const float w1 = w_s[(r0 + 8) * 9 + ch];
                const float w2 = w_s[(r0 + 16) * 9 + ch];
                const float w3 = w_s[(r0 + 24) * 9 + ch];
                #pragma unroll
                for (int nt = 0; nt < 8; nt++) {
                    uint32_t u0, u1, u2, u3;
                    if (ci == 0) {
                        u0 = hp[nt];  u1 = hp[8 + nt];
                        u2 = lds32(estg + (uint32_t)((nt * 2) * 2048));
                        u3 = lds32(estg + (uint32_t)((nt * 2 + 1) * 2048));
                    } else {
                        u0 = hp[16 + nt]; u1 = hp[24 + nt];
                        u2 = hp[32 + nt]; u3 = hp[40 + nt];
                    }
                    const float2 e0 = __half22float2(*reinterpret_cast<const __half2*>(&u0));
                    const float2 e1 = __half22float2(*reinterpret_cast<const __half2*>(&u1));
                    const float2 e2 = __half22float2(*reinterpret_cast<const __half2*>(&u2));
                    const float2 e3 = __half22float2(*reinterpret_cast<const __half2*>(&u3));
                    float2 o;
                    o.x = e0.x * w0;  o.y = e0.y * w0;
                    *reinterpret_cast<float2*>(qt + (size_t)r0 * KC + colb + nt * 8) = o;
                    o.x = e1.x * w1;  o.y = e1.y * w1;
                    *reinterpret_cast<float2*>(qt + (size_t)(r0 + 8) * KC + colb + nt * 8) = o;
                    o.x = e2.x * w2;  o.y = e2.y * w2;
                    *reinterpret_cast<float2*>(qt + (size_t)(r0 + 16) * KC + colb + nt * 8) = o;
                    o.x = e3.x * w3;  o.y = e3.y * w3;
                    *reinterpret_cast<float2*>(qt + (size_t)(r0 + 24) * KC + colb + nt * 8) = o;
                }
            }
        }
    } // tile loop

    if (tid == 0) g_loss_partial[bid] = cta_loss;

    // ---- last-CTA loss finalize (deterministic fixed-order sum) ------------
    __threadfence();
    if (tid == 0) {
        const unsigned int old = atomicAdd(&g_done, 1u);
        *flag_s = (old == (unsigned int)(NCTAS - 1)) ? 1u : 0u;
    }
    __syncthreads();
    if (*flag_s) {
        double a = (tid < NCTAS) ? (double)g_loss_partial[tid] : 0.0;
        #pragma unroll
        for (int o = 16; o; o >>= 1) a += __shfl_xor_sync(~0u, a, o);
        double* dred = reinterpret_cast<double*>(smem + OFF_RED + 128);
        if (lane == 0) dred[wid] = a;
        __syncthreads();
        if (tid == 0) {
            double t = 0.0;
            #pragma unroll
            for (int i = 0; i < 16; i++) t += dred[i];
            if (loss_out) *loss_out = (float)(t / (double)B_ROWS);
            g_done = 0;   // reset for next graph replay
        }
    }
}

// ============================================================================
// Launch
// ============================================================================
extern "C" void kernel_launch(void* const* d_in, const int* in_sizes, int n_in,
                              void* d_out, int out_size) {
    const float* z  = (const float*)d_in[0];
    const float* cc = (const float*)d_in[1];
    float* q = (float*)d_out;

    const long long q_elems = (long long)B_ROWS * KC;  // 67108864
    float* loss_out = ((long long)out_size > q_elems) ? (q + q_elems) : nullptr;

    cudaFuncSetAttribute(soft_kmeans_kernel,
                         cudaFuncAttributeMaxDynamicSharedMemorySize, SMEM_BYTES);
    soft_kmeans_kernel<<<NCTAS, 512, SMEM_BYTES>>>(z, cc, q, loss_out);
}

// round 13
// speedup vs baseline: 1.4744x; 1.0070x over previous
#include <cuda_runtime.h>
#include <cuda_bf16.h>
#include <cuda_fp16.h>
#include <cstdint>

// ============================================================================
// Problem constants
// ============================================================================
static constexpr int B_ROWS = 131072;
static constexpr int KC     = 512;
static constexpr int TM     = 128;
static constexpr int NTILES = B_ROWS / TM;   // 1024
static constexpr int NCTAS  = 148;           // persistent grid

static constexpr float LOG2E = 1.4426950408889634f;
static constexpr float LN2   = 0.6931471805599453f;

// ============================================================================
// SMEM layout (bytes) — tile regions 1024-aligned for SW128
// ============================================================================
static constexpr int OFF_ZSQ  = 0;        // 128 f32 (log2e-scaled)
static constexpr int OFF_CSQ  = 512;      // 512 f32 (NEGATED, log2e-scaled)
static constexpr int OFF_W    = 2560;     // 128*9 f32 (chunk running-max snapshots)
static constexpr int OFF_MST  = 7168;     // 4 grp x 128 rows x 4 f32; pad slots of
                                          //   grp0/grp1 hold Mv / inv after merge
static constexpr int OFF_RED  = 15360;    // warp partials + flag + dbl scratch (1 KB)
static constexpr int OFF_AHI  = 16384;    // z-hi 128x128B = 16 KB
static constexpr int OFF_ALO  = 32768;    // z-lo 16 KB
static constexpr int OFF_ESTG = 49152;    // e-stage: chunk0 rows r2/r3, 32 KB
static constexpr int OFF_BHI  = 81920;    // c-hi  512 x 128B = 64 KB (PERSISTENT)
static constexpr int OFF_BLO  = 147456;   // 64 KB (PERSISTENT)
static constexpr int SMEM_BYTES = 212992; // 208 KB

__device__ float g_loss_partial[NCTAS];
__device__ unsigned int g_done;   // zero-init; reset by last CTA each run

#define SWZ(o) ((o) ^ (((o) >> 3) & 0x70))

// ============================================================================
// Helpers
// ============================================================================
__device__ __forceinline__ uint32_t smem_u32(const void* p) {
    uint32_t a;
    asm("{ .reg .u64 t; cvta.to.shared.u64 t, %1; cvt.u32.u64 %0, t; }" : "=r"(a) : "l"(p));
    return a;
}

__device__ __forceinline__ float ex2f(float x) {   // bare MUFU.EX2 (log2 domain)
    float r;
    asm("ex2.approx.ftz.f32 %0, %1;" : "=f"(r) : "f"(x));
    return r;
}

__device__ __forceinline__ void ldsm4(uint32_t r[4], uint32_t addr) {
    asm volatile("ldmatrix.sync.aligned.m8n8.x4.shared.b16 {%0,%1,%2,%3}, [%4];"
                 : "=r"(r[0]), "=r"(r[1]), "=r"(r[2]), "=r"(r[3]) : "r"(addr));
}

__device__ __forceinline__ void mma16816(float* d, const uint32_t* a, uint32_t b0, uint32_t b1) {
    asm volatile("mma.sync.aligned.m16n8k16.row.col.f32.bf16.bf16.f32 "
                 "{%0,%1,%2,%3}, {%4,%5,%6,%7}, {%8,%9}, {%0,%1,%2,%3};"
                 : "+f"(d[0]), "+f"(d[1]), "+f"(d[2]), "+f"(d[3])
                 : "r"(a[0]), "r"(a[1]), "r"(a[2]), "r"(a[3]), "r"(b0), "r"(b1));
}

__device__ __forceinline__ void split2(float x, float y, uint32_t& hi, uint32_t& lo) {
    __nv_bfloat16 hx = __float2bfloat16(x), hy = __float2bfloat16(y);
    float rx = x - __bfloat162float(hx);
    float ry = y - __bfloat162float(hy);
    __nv_bfloat162 h(hx, hy);
    __nv_bfloat162 l(__float2bfloat16(rx), __float2bfloat16(ry));
    hi = *reinterpret_cast<uint32_t*>(&h);
    lo = *reinterpret_cast<uint32_t*>(&l);
}

__device__ __forceinline__ void sts32(uint32_t addr, uint32_t v) {
    asm volatile("st.shared.b32 [%0], %1;" :: "r"(addr), "r"(v) : "memory");
}
__device__ __forceinline__ uint32_t lds32(uint32_t addr) {
    uint32_t v;
    asm volatile("ld.shared.b32 %0, [%1];" : "=r"(v) : "r"(addr));
    return v;
}

// One 64-col chunk of cross' for an m32 warp tile (3 split terms fused).
// acc[64]: [0..31] rows r0/r1, [32..63] rows r2/r3.
__device__ __forceinline__ void compute_chunk(
    float acc[64], uint32_t sb, uint32_t chbase,
    uint32_t aoff0, uint32_t aoff1, uint32_t bRowL, uint32_t bK16)
{
    #pragma unroll
    for (int i = 0; i < 64; i++) acc[i] = 0.f;
    #pragma unroll
    for (int ks = 0; ks < 4; ks++) {
        uint32_t a0[4], a1[4], l0[4], l1[4];
        ldsm4(a0, sb + OFF_AHI + SWZ(aoff0 + ks * 32));
        ldsm4(a1, sb + OFF_AHI + SWZ(aoff1 + ks * 32));
        ldsm4(l0, sb + OFF_ALO + SWZ(aoff0 + ks * 32));
        ldsm4(l1, sb + OFF_ALO + SWZ(aoff1 + ks * 32));
        #pragma unroll
        for (int p = 0; p < 4; p++) {
            const uint32_t bo = (chbase + p * 16 + bRowL) * 128 + bK16 + ks * 32;
            uint32_t bh[4], bl[4];
            ldsm4(bh, sb + OFF_BHI + SWZ(bo));
            ldsm4(bl, sb + OFF_BLO + SWZ(bo));
            float* A0 = acc + (p * 2) * 4;
            float* A1 = acc + (p * 2 + 1) * 4;
            float* B0 = acc + 32 + (p * 2) * 4;
            float* B1 = acc + 32 + (p * 2 + 1) * 4;
            mma16816(A0, a0, bh[0], bh[1]); mma16816(A1, a0, bh[2], bh[3]);
            mma16816(A0, a0, bl[0], bl[1]); mma16816(A1, a0, bl[2], bl[3]);
            mma16816(A0, l0, bh[0], bh[1]); mma16816(A1, l0, bh[2], bh[3]);
            mma16816(B0, a1, bh[0], bh[1]); mma16816(B1, a1, bh[2], bh[3]);
            mma16816(B0, a1, bl[0], bl[1]); mma16816(B1, a1, bl[2], bl[3]);
            mma16816(B0, l1, bh[0], bh[1]); mma16816(B1, l1, bh[2], bh[3]);
        }
    }
}

// ============================================================================
// Persistent kernel: 148 CTAs x 512 threads (16 warps)
// warp = m32-tile (mt = wid&3) x n128 col-group (grp = wid>>2, chunks 2g,2g+1)
// e: chunk0 r0/r1 + chunk1 all rows in regs (hp[48]); chunk0 r2/r3 in SMEM.
// 3 barriers/tile; z via LDG with L2 prefetch issued one tile ahead.
// ============================================================================
__global__ void __launch_bounds__(512, 1)
soft_kmeans_kernel(const float* __restrict__ z, const float* __restrict__ cc,
                   float* __restrict__ q_out, float* __restrict__ loss_out) {
    extern __shared__ char smem[];
    const uint32_t sb = smem_u32(smem);
    const int tid  = threadIdx.x;
    const int lane = tid & 31;
    const int wid  = tid >> 5;
    const int bid  = blockIdx.x;
    const int mt   = wid & 3;     // rows mt*32 .. mt*32+31
    const int grp  = wid >> 2;    // cols grp*128 .. grp*128+127

    float* zsq_s = reinterpret_cast<float*>(smem + OFF_ZSQ);
    float* csq_s = reinterpret_cast<float*>(smem + OFF_CSQ);
    float* w_s   = reinterpret_cast<float*>(smem + OFF_W);
    float* mst_s = reinterpret_cast<float*>(smem + OFF_MST);
    float* red_s = reinterpret_cast<float*>(smem + OFF_RED);
    unsigned int* flag_s = reinterpret_cast<unsigned int*>(smem + OFF_RED + 64);

    const float4* z4 = reinterpret_cast<const float4*>(z);

    // ---- L2-prefetch first z tile ------------------------------------------
    {
        const char* pz = reinterpret_cast<const char*>(z4 + (size_t)bid * 2048) + tid * 256;
        asm volatile("prefetch.global.L2 [%0];" :: "l"(pz));
        asm volatile("prefetch.global.L2 [%0];" :: "l"(pz + 128));
    }

    // ---- split all 512 centers ONCE (persistent for all tiles) -------------
    {
        const float4* ct = reinterpret_cast<const float4*>(cc);
        #pragma unroll 4
        for (int it = 0; it < 16; it++) {
            const int idx = it * 512 + tid;
            const int row = idx >> 4, c4 = idx & 15;
            const float4 v = ct[idx];
            float sq = v.x * v.x + v.y * v.y + v.z * v.z + v.w * v.w;
            sq += __shfl_xor_sync(~0u, sq, 1);
            sq += __shfl_xor_sync(~0u, sq, 2);
            sq += __shfl_xor_sync(~0u, sq, 4);
            sq += __shfl_xor_sync(~0u, sq, 8);
            if ((lane & 15) == 0) csq_s[row] = -sq * LOG2E;  // ready-to-add addend
            uint2 hi, lo;
            split2(v.x, v.y, hi.x, lo.x);
            split2(v.z, v.w, hi.y, lo.y);
            const uint32_t so = SWZ((uint32_t)(row * 128 + c4 * 8));
            *reinterpret_cast<uint2*>(smem + OFF_BHI + so) = hi;
            *reinterpret_cast<uint2*>(smem + OFF_BLO + so) = lo;
        }
    }

    // ---- lane decodes (m32 tile) -------------------------------------------
    const uint32_t aCol16 = ((lane >> 4) & 1) * 16;
    const uint32_t aRow0  = (uint32_t)(mt * 32 + ((lane >> 3) & 1) * 8 + (lane & 7));
    const uint32_t aoff0  = aRow0 * 128 + aCol16;
    const uint32_t aoff1  = (aRow0 + 16) * 128 + aCol16;
    const uint32_t bRowL  = ((lane >> 4) & 1) * 8 + (lane & 7);
    const uint32_t bK16   = ((lane >> 3) & 1) * 16;

    const int r0 = mt * 32 + (lane >> 2);   // r1=r0+8, r2=r0+16, r3=r0+24
    const uint32_t estg = sb + OFF_ESTG + (uint32_t)tid * 4;  // slot stride 2048

    float cta_loss = 0.f;

    // ======================= tile loop =====================================
    for (int tile = bid; tile < NTILES; tile += NCTAS) {

        // ---- split z tile: LDG (L2-hot from prefetch) -> A hi/lo -----------
        {
            const float SC = 2.0f * LOG2E;
            const float4* zt = z4 + (size_t)tile * 2048;
            #pragma unroll
            for (int it = 0; it < 4; it++) {
                const int idx = it * 512 + tid;
                const int row = idx >> 4, c4 = idx & 15;
                const float4 v = zt[idx];
                float sq = v.x * v.x + v.y * v.y + v.z * v.z + v.w * v.w;
                sq += __shfl_xor_sync(~0u, sq, 1);
                sq += __shfl_xor_sync(~0u, sq, 2);
                sq += __shfl_xor_sync(~0u, sq, 4);
                sq += __shfl_xor_sync(~0u, sq, 8);
                if ((lane & 15) == 0) zsq_s[row] = sq * LOG2E;   // zq' (log2)
                uint2 hi, lo;
                split2(SC * v.x, SC * v.y, hi.x, lo.x);
                split2(SC * v.z, SC * v.w, hi.y, lo.y);
                const uint32_t so = SWZ((uint32_t)(row * 128 + c4 * 8));
                *reinterpret_cast<uint2*>(smem + OFF_AHI + so) = hi;
                *reinterpret_cast<uint2*>(smem + OFF_ALO + so) = lo;
            }
        }
        __syncthreads();   // sync1: A/zsq visible (covers B on first tile)

        // ---- PASS 1: 2 chunks of 64 cols; 4 row streams; e -> hp/SMEM ------
        float m0, s0 = 0.f, t0 = 0.f;
        float m1, s1 = 0.f, t1 = 0.f;
        float m2, s2 = 0.f, t2 = 0.f;
        float m3, s3 = 0.f, t3 = 0.f;
        uint32_t hp[48];

        #pragma unroll
        for (int ci = 0; ci < 2; ci++) {
            const uint32_t chbase = (uint32_t)(grp * 128 + ci * 64);

            float acc[64];
            compute_chunk(acc, sb, chbase, aoff0, aoff1, bRowL, bK16);

            // u = cross' + (-csq'); chunk max per row stream
            float cm0 = -1e30f, cm1 = -1e30f, cm2 = -1e30f, cm3 = -1e30f;
            #pragma unroll
            for (int nt = 0; nt < 8; nt++) {
                const float2 cs = *reinterpret_cast<const float2*>(
                    csq_s + chbase + nt * 8 + (lane & 3) * 2);
                float* A = acc + nt * 4;
                float* B = acc + 32 + nt * 4;
                A[0] += cs.x;  A[1] += cs.y;   // r0
                A[2] += cs.x;  A[3] += cs.y;   // r1
                B[0] += cs.x;  B[1] += cs.y;   // r2
                B[2] += cs.x;  B[3] += cs.y;   // r3
                cm0 = fmaxf(cm0, fmaxf(A[0], A[1]));
                cm1 = fmaxf(cm1, fmaxf(A[2], A[3]));
                cm2 = fmaxf(cm2, fmaxf(B[0], B[1]));
                cm3 = fmaxf(cm3, fmaxf(B[2], B[3]));
            }
            cm0 = fmaxf(cm0, __shfl_xor_sync(~0u, cm0, 1));
            cm0 = fmaxf(cm0, __shfl_xor_sync(~0u, cm0, 2));
            cm1 = fmaxf(cm1, __shfl_xor_sync(~0u, cm1, 1));
            cm1 = fmaxf(cm1, __shfl_xor_sync(~0u, cm1, 2));
            cm2 = fmaxf(cm2, __shfl_xor_sync(~0u, cm2, 1));
            cm2 = fmaxf(cm2, __shfl_xor_sync(~0u, cm2, 2));
            cm3 = fmaxf(cm3, __shfl_xor_sync(~0u, cm3, 1));
            cm3 = fmaxf(cm3, __shfl_xor_sync(~0u, cm3, 2));
            if (ci == 0) {
                // first chunk: s=t=0, no rescale needed
                m0 = cm0; m1 = cm1; m2 = cm2; m3 = cm3;
            } else {
                const float nm0 = fmaxf(m0, cm0), f0 = ex2f(m0 - nm0);
                const float nm1 = fmaxf(m1, cm1), f1 = ex2f(m1 - nm1);
                const float nm2 = fmaxf(m2, cm2), f2 = ex2f(m2 - nm2);
                const float nm3 = fmaxf(m3, cm3), f3 = ex2f(m3 - nm3);
                s0 *= f0; t0 *= f0; m0 = nm0;
                s1 *= f1; t1 *= f1; m1 = nm1;
                s2 *= f2; t2 *= f2; m2 = nm2;
                s3 *= f3; t3 *= f3; m3 = nm3;
            }

            #pragma unroll
            for (int nt = 0; nt < 8; nt++) {
                float* A = acc + nt * 4;
                float* B = acc + 32 + nt * 4;
                const float e00 = ex2f(A[0] - m0), e01 = ex2f(A[1] - m0);
                const float e10 = ex2f(A[2] - m1), e11 = ex2f(A[3] - m1);
                const float e20 = ex2f(B[0] - m2), e21 = ex2f(B[1] - m2);
                const float e30 = ex2f(B[2] - m3), e31 = ex2f(B[3] - m3);
                s0 += e00 + e01;  t0 += e00 * A[0] + e01 * A[1];   // t_u = sum e*u
                s1 += e10 + e11;  t1 += e10 * A[2] + e11 * A[3];
                s2 += e20 + e21;  t2 += e20 * B[0] + e21 * B[1];
                s3 += e30 + e31;  t3 += e30 * B[2] + e31 * B[3];
                const __half2 h0 = __floats2half2_rn(e00, e01);
                const __half2 h1 = __floats2half2_rn(e10, e11);
                const __half2 h2 = __floats2half2_rn(e20, e21);
                const __half2 h3 = __floats2half2_rn(e30, e31);
                if (ci == 0) {
                    hp[nt]     = *reinterpret_cast<const uint32_t*>(&h0);
                    hp[8 + nt] = *reinterpret_cast<const uint32_t*>(&h1);
                    sts32(estg + (uint32_t)((nt * 2) * 2048),
                          *reinterpret_cast<const uint32_t*>(&h2));
                    sts32(estg + (uint32_t)((nt * 2 + 1) * 2048),
                          *reinterpret_cast<const uint32_t*>(&h3));
                } else {
                    hp[16 + nt] = *reinterpret_cast<const uint32_t*>(&h0);
                    hp[24 + nt] = *reinterpret_cast<const uint32_t*>(&h1);
                    hp[32 + nt] = *reinterpret_cast<const uint32_t*>(&h2);
                    hp[40 + nt] = *reinterpret_cast<const uint32_t*>(&h3);
                }
            }
            if ((lane & 3) == 0) {
                const int ch = grp * 2 + ci;
                w_s[r0 * 9 + ch]        = m0;
                w_s[(r0 + 8) * 9 + ch]  = m1;
                w_s[(r0 + 16) * 9 + ch] = m2;
                w_s[(r0 + 24) * 9 + ch] = m3;
            }
        }

        // ---- group-local row reductions + publish (m, s, t_u) --------------
        s0 += __shfl_xor_sync(~0u, s0, 1);  s0 += __shfl_xor_sync(~0u, s0, 2);
        t0 += __shfl_xor_sync(~0u, t0, 1);  t0 += __shfl_xor_sync(~0u, t0, 2);
        s1 += __shfl_xor_sync(~0u, s1, 1);  s1 += __shfl_xor_sync(~0u, s1, 2);
        t1 += __shfl_xor_sync(~0u, t1, 1);  t1 += __shfl_xor_sync(~0u, t1, 2);
        s2 += __shfl_xor_sync(~0u, s2, 1);  s2 += __shfl_xor_sync(~0u, s2, 2);
        t2 += __shfl_xor_sync(~0u, t2, 1);  t2 += __shfl_xor_sync(~0u, t2, 2);
        s3 += __shfl_xor_sync(~0u, s3, 1);  s3 += __shfl_xor_sync(~0u, s3, 2);
        t3 += __shfl_xor_sync(~0u, t3, 1);  t3 += __shfl_xor_sync(~0u, t3, 2);
        if ((lane & 3) == 0) {
            float* p0 = mst_s + (size_t)(grp * 128 + r0) * 4;
            p0[0] = m0; p0[1] = s0; p0[2] = t0;
            float* p1 = mst_s + (size_t)(grp * 128 + r0 + 8) * 4;
            p1[0] = m1; p1[1] = s1; p1[2] = t1;
            float* p2 = mst_s + (size_t)(grp * 128 + r0 + 16) * 4;
            p2[0] = m2; p2[1] = s2; p2[2] = t2;
            float* p3 = mst_s + (size_t)(grp * 128 + r0 + 24) * 4;
            p3[0] = m3; p3[1] = s3; p3[2] = t3;
        }
        __syncthreads();   // sync2: mst published

        // ---- merge 4 groups per row (thread = row): Mv, inv, loss only -----
        float lossr = 0.f;
        if (tid < TM) {
            float Mv = -1e30f;
            float mg[4], sg[4], tg[4];
            #pragma unroll
            for (int g = 0; g < 4; g++) {
                const float* p = mst_s + (size_t)(g * 128 + tid) * 4;
                mg[g] = p[0]; sg[g] = p[1]; tg[g] = p[2];
                Mv = fmaxf(Mv, mg[g]);
            }
            float sF = 0.f, tF = 0.f;
            #pragma unroll
            for (int g = 0; g < 4; g++) {
                const float f = ex2f(mg[g] - Mv);
                sF += sg[g] * f; tF += tg[g] * f;
            }
            const float inv = 1.f / sF;
            lossr = (zsq_s[tid] - tF * inv) * LN2;
            mst_s[(size_t)tid * 4 + 3]         = Mv;    // pad slot of grp0 row
            mst_s[(size_t)(128 + tid) * 4 + 3] = inv;   // pad slot of grp1 row
        }
        #pragma unroll
        for (int o = 16; o; o >>= 1) lossr += __shfl_xor_sync(~0u, lossr, o);
        if (wid < 4 && lane == 0) red_s[wid] = lossr;
        __syncthreads();   // sync3: Mv/inv/red_s ready
        if (tid == 0)
            cta_loss += red_s[0] + red_s[1] + red_s[2] + red_s[3];

        // ---- L2-prefetch next z tile (overlaps pass 2) ---------------------
        {
            const int ntile = tile + NCTAS;
            if (ntile < NTILES) {
                const char* pz = reinterpret_cast<const char*>(
                    z4 + (size_t)ntile * 2048) + tid * 256;
                asm volatile("prefetch.global.L2 [%0];" :: "l"(pz));
                asm volatile("prefetch.global.L2 [%0];" :: "l"(pz + 128));
            }
        }

        // ---- PASS 2: q stores from registers + staged SMEM -----------------
        {
            float* qt = q_out + (size_t)tile * TM * KC;
            const int c2 = (lane & 3) * 2;
            // per-row merge outputs (4 row streams)
            float Mvj[4], ivj[4];
            #pragma unroll
            for (int j = 0; j < 4; j++) {
                const int r = r0 + j * 8;
                Mvj[j] = mst_s[(size_t)r * 4 + 3];
                ivj[j] = mst_s[(size_t)(128 + r) * 4 + 3];
            }
            #pragma unroll
            for (int ci = 0; ci < 2; ci++) {
                const int ch = grp * 2 + ci;
                const int colb = grp * 128 + ci * 64 + c2;
                const float w0 = ex2f(w_s[r0 * 9 + ch]        - Mvj[0]) * ivj[0];
                const float w1 = ex2f(w_s[(r0 + 8) * 9 + ch]  - Mvj[1]) * ivj[1];
                const float w2 = ex2f(w_s[(r0 + 16) * 9 + ch] - Mvj[2]) * ivj[2];
                const float w3 = ex2f(w_s[(r0 + 24) * 9 + ch] - Mvj[3]) * ivj[3];
                #pragma unroll
                for (int nt = 0; nt < 8; nt++) {
                    uint32_t u0, u1, u2, u3;
                    if (ci == 0) {
                        u0 = hp[nt];  u1 = hp[8 + nt];
                        u2 = lds32(estg + (uint32_t)((nt * 2) * 2048));
                        u3 = lds32(estg + (uint32_t)((nt * 2 + 1) * 2048));
                    } else {
                        u0 = hp[16 + nt]; u1 = hp[24 + nt];
                        u2 = hp[32 + nt]; u3 = hp[40 + nt];
                    }
                    const float2 e0 = __half22float2(*reinterpret_cast<const __half2*>(&u0));
                    const float2 e1 = __half22float2(*reinterpret_cast<const __half2*>(&u1));
                    const float2 e2 = __half22float2(*reinterpret_cast<const __half2*>(&u2));
                    const float2 e3 = __half22float2(*reinterpret_cast<const __half2*>(&u3));
                    float2 o;
                    o.x = e0.x * w0;  o.y = e0.y * w0;
                    *reinterpret_cast<float2*>(qt + (size_t)r0 * KC + colb + nt * 8) = o;
                    o.x = e1.x * w1;  o.y = e1.y * w1;
                    *reinterpret_cast<float2*>(qt + (size_t)(r0 + 8) * KC + colb + nt * 8) = o;
                    o.x = e2.x * w2;  o.y = e2.y * w2;
                    *reinterpret_cast<float2*>(qt + (size_t)(r0 + 16) * KC + colb + nt * 8) = o;
                    o.x = e3.x * w3;  o.y = e3.y * w3;
                    *reinterpret_cast<float2*>(qt + (size_t)(r0 + 24) * KC + colb + nt * 8) = o;
                }
            }
        }
    } // tile loop

    if (tid == 0) g_loss_partial[bid] = cta_loss;

    // ---- last-CTA loss finalize (deterministic fixed-order sum) ------------
    __threadfence();
    if (tid == 0) {
        const unsigned int old = atomicAdd(&g_done, 1u);
        *flag_s = (old == (unsigned int)(NCTAS - 1)) ? 1u : 0u;
    }
    __syncthreads();
    if (*flag_s) {
        double a = (tid < NCTAS) ? (double)g_loss_partial[tid] : 0.0;
        #pragma unroll
        for (int o = 16; o; o >>= 1) a += __shfl_xor_sync(~0u, a, o);
        double* dred = reinterpret_cast<double*>(smem + OFF_RED + 128);
        if (lane == 0) dred[wid] = a;
        __syncthreads();
        if (tid == 0) {
            double t = 0.0;
            #pragma unroll
            for (int i = 0; i < 16; i++) t += dred[i];
            if (loss_out) *loss_out = (float)(t / (double)B_ROWS);
            g_done = 0;   // reset for next graph replay
        }
    }
}

// ============================================================================
// Launch
// ============================================================================
extern "C" void kernel_launch(void* const* d_in, const int* in_sizes, int n_in,
                              void* d_out, int out_size) {
    const float* z  = (const float*)d_in[0];
    const float* cc = (const float*)d_in[1];
    float* q = (float*)d_out;

    const long long q_elems = (long long)B_ROWS * KC;  // 67108864
    float* loss_out = ((long long)out_size > q_elems) ? (q + q_elems) : nullptr;

    cudaFuncSetAttribute(soft_kmeans_kernel,
                         cudaFuncAttributeMaxDynamicSharedMemorySize, SMEM_BYTES);
    soft_kmeans_kernel<<<NCTAS, 512, SMEM_BYTES>>>(z, cc, q, loss_out);
}

// round 14
// speedup vs baseline: 1.4852x; 1.0073x over previous
#include <cuda_runtime.h>
#include <cuda_bf16.h>
#include <cuda_fp16.h>
#include <cstdint>

// ============================================================================
// Problem constants
// ============================================================================
static constexpr int B_ROWS = 131072;
static constexpr int KC     = 512;
static constexpr int TM     = 128;
static constexpr int NTILES = B_ROWS / TM;   // 1024
static constexpr int NCTAS  = 148;           // persistent grid

static constexpr float LOG2E = 1.4426950408889634f;
static constexpr float LN2   = 0.6931471805599453f;

// ============================================================================
// SMEM layout (bytes) — tile regions 1024-aligned for SW128
// ============================================================================
static constexpr int OFF_ZSQ  = 0;        // 128 f32 (log2e-scaled)
static constexpr int OFF_CSQ  = 512;      // 512 f32 (NEGATED, log2e-scaled)
static constexpr int OFF_W    = 2560;     // 128*9 f32 (chunk running-max snapshots)
static constexpr int OFF_MST  = 7168;     // 4 grp x 128 rows x 4 f32; pad slots of
                                          //   grp0/grp1 hold Mv / inv after merge
static constexpr int OFF_RED  = 15360;    // warp partials + flag + dbl scratch (1 KB)
static constexpr int OFF_AHI  = 16384;    // z-hi 128x128B = 16 KB
static constexpr int OFF_ALO  = 32768;    // z-lo 16 KB
static constexpr int OFF_ESTG = 49152;    // e-stage: chunk0 rows r2/r3, 32 KB
static constexpr int OFF_BHI  = 81920;    // c-hi  512 x 128B = 64 KB (PERSISTENT)
static constexpr int OFF_BLO  = 147456;   // 64 KB (PERSISTENT)
static constexpr int SMEM_BYTES = 212992; // 208 KB

__device__ float g_loss_partial[NCTAS];
__device__ unsigned int g_done;   // zero-init; reset by last CTA each run

#define SWZ(o) ((o) ^ (((o) >> 3) & 0x70))

// ============================================================================
// Helpers
// ============================================================================
__device__ __forceinline__ uint32_t smem_u32(const void* p) {
    uint32_t a;
    asm("{ .reg .u64 t; cvta.to.shared.u64 t, %1; cvt.u32.u64 %0, t; }" : "=r"(a) : "l"(p));
    return a;
}

__device__ __forceinline__ float ex2f(float x) {   // bare MUFU.EX2 (log2 domain)
    float r;
    asm("ex2.approx.ftz.f32 %0, %1;" : "=f"(r) : "f"(x));
    return r;
}

// ---- packed f32x2 (Blackwell family: double-rate FP32) ---------------------
__device__ __forceinline__ uint64_t pk2(float a, float b) {
    uint64_t r;
    asm("mov.b64 %0, {%1, %2};" : "=l"(r) : "f"(a), "f"(b));
    return r;
}
__device__ __forceinline__ void upk2(float& a, float& b, uint64_t p) {
    asm("mov.b64 {%0, %1}, %2;" : "=f"(a), "=f"(b) : "l"(p));
}
__device__ __forceinline__ uint64_t add2(uint64_t a, uint64_t b) {
    uint64_t r;
    asm("add.rn.f32x2 %0, %1, %2;" : "=l"(r) : "l"(a), "l"(b));
    return r;
}
__device__ __forceinline__ uint64_t mul2(uint64_t a, uint64_t b) {
    uint64_t r;
    asm("mul.rn.f32x2 %0, %1, %2;" : "=l"(r) : "l"(a), "l"(b));
    return r;
}
__device__ __forceinline__ uint64_t fma2(uint64_t a, uint64_t b, uint64_t c) {
    uint64_t r;
    asm("fma.rn.f32x2 %0, %1, %2, %3;" : "=l"(r) : "l"(a), "l"(b), "l"(c));
    return r;
}

__device__ __forceinline__ void ldsm4(uint32_t r[4], uint32_t addr) {
    asm volatile("ldmatrix.sync.aligned.m8n8.x4.shared.b16 {%0,%1,%2,%3}, [%4];"
                 : "=r"(r[0]), "=r"(r[1]), "=r"(r[2]), "=r"(r[3]) : "r"(addr));
}

__device__ __forceinline__ void mma16816(float* d, const uint32_t* a, uint32_t b0, uint32_t b1) {
    asm volatile("mma.sync.aligned.m16n8k16.row.col.f32.bf16.bf16.f32 "
                 "{%0,%1,%2,%3}, {%4,%5,%6,%7}, {%8,%9}, {%0,%1,%2,%3};"
                 : "+f"(d[0]), "+f"(d[1]), "+f"(d[2]), "+f"(d[3])
                 : "r"(a[0]), "r"(a[1]), "r"(a[2]), "r"(a[3]), "r"(b0), "r"(b1));
}

__device__ __forceinline__ void split2(float x, float y, uint32_t& hi, uint32_t& lo) {
    __nv_bfloat16 hx = __float2bfloat16(x), hy = __float2bfloat16(y);
    float rx = x - __bfloat162float(hx);
    float ry = y - __bfloat162float(hy);
    __nv_bfloat162 h(hx, hy);
    __nv_bfloat162 l(__float2bfloat16(rx), __float2bfloat16(ry));
    hi = *reinterpret_cast<uint32_t*>(&h);
    lo = *reinterpret_cast<uint32_t*>(&l);
}

__device__ __forceinline__ void sts32(uint32_t addr, uint32_t v) {
    asm volatile("st.shared.b32 [%0], %1;" :: "r"(addr), "r"(v) : "memory");
}
__device__ __forceinline__ uint32_t lds32(uint32_t addr) {
    uint32_t v;
    asm volatile("ld.shared.b32 %0, [%1];" : "=r"(v) : "r"(addr));
    return v;
}

// One 64-col chunk of cross' for an m32 warp tile (3 split terms fused).
// acc[64]: [0..31] rows r0/r1, [32..63] rows r2/r3.
__device__ __forceinline__ void compute_chunk(
    float acc[64], uint32_t sb, uint32_t chbase,
    uint32_t aoff0, uint32_t aoff1, uint32_t bRowL, uint32_t bK16)
{
    #pragma unroll
    for (int i = 0; i < 64; i++) acc[i] = 0.f;
    #pragma unroll
    for (int ks = 0; ks < 4; ks++) {
        uint32_t a0[4], a1[4], l0[4], l1[4];
        ldsm4(a0, sb + OFF_AHI + SWZ(aoff0 + ks * 32));
        ldsm4(a1, sb + OFF_AHI + SWZ(aoff1 + ks * 32));
        ldsm4(l0, sb + OFF_ALO + SWZ(aoff0 + ks * 32));
        ldsm4(l1, sb + OFF_ALO + SWZ(aoff1 + ks * 32));
        #pragma unroll
        for (int p = 0; p < 4; p++) {
            const uint32_t bo = (chbase + p * 16 + bRowL) * 128 + bK16 + ks * 32;
            uint32_t bh[4], bl[4];
            ldsm4(bh, sb + OFF_BHI + SWZ(bo));
            ldsm4(bl, sb + OFF_BLO + SWZ(bo));
            float* A0 = acc + (p * 2) * 4;
            float* A1 = acc + (p * 2 + 1) * 4;
            float* B0 = acc + 32 + (p * 2) * 4;
            float* B1 = acc + 32 + (p * 2 + 1) * 4;
            mma16816(A0, a0, bh[0], bh[1]); mma16816(A1, a0, bh[2], bh[3]);
            mma16816(A0, a0, bl[0], bl[1]); mma16816(A1, a0, bl[2], bl[3]);
            mma16816(A0, l0, bh[0], bh[1]); mma16816(A1, l0, bh[2], bh[3]);
            mma16816(B0, a1, bh[0], bh[1]); mma16816(B1, a1, bh[2], bh[3]);
            mma16816(B0, a1, bl[0], bl[1]); mma16816(B1, a1, bl[2], bl[3]);
            mma16816(B0, l1, bh[0], bh[1]); mma16816(B1, l1, bh[2], bh[3]);
        }
    }
}

// ============================================================================
// Persistent kernel: 148 CTAs x 512 threads (16 warps)
// warp = m32-tile (mt = wid&3) x n128 col-group (grp = wid>>2, chunks 2g,2g+1)
// e: chunk0 r0/r1 + chunk1 all rows in regs (hp[48]); chunk0 r2/r3 in SMEM.
// epilogue + pass2 use packed f32x2 math.
// ============================================================================
__global__ void __launch_bounds__(512, 1)
soft_kmeans_kernel(const float* __restrict__ z, const float* __restrict__ cc,
                   float* __restrict__ q_out, float* __restrict__ loss_out) {
    extern __shared__ char smem[];
    const uint32_t sb = smem_u32(smem);
    const int tid  = threadIdx.x;
    const int lane = tid & 31;
    const int wid  = tid >> 5;
    const int bid  = blockIdx.x;
    const int mt   = wid & 3;     // rows mt*32 .. mt*32+31
    const int grp  = wid >> 2;    // cols grp*128 .. grp*128+127

    float* zsq_s = reinterpret_cast<float*>(smem + OFF_ZSQ);
    float* csq_s = reinterpret_cast<float*>(smem + OFF_CSQ);
    float* w_s   = reinterpret_cast<float*>(smem + OFF_W);
    float* mst_s = reinterpret_cast<float*>(smem + OFF_MST);
    float* red_s = reinterpret_cast<float*>(smem + OFF_RED);
    unsigned int* flag_s = reinterpret_cast<unsigned int*>(smem + OFF_RED + 64);

    const float4* z4 = reinterpret_cast<const float4*>(z);

    // ---- L2-prefetch first z tile ------------------------------------------
    {
        const char* pz = reinterpret_cast<const char*>(z4 + (size_t)bid * 2048) + tid * 256;
        asm volatile("prefetch.global.L2 [%0];" :: "l"(pz));
        asm volatile("prefetch.global.L2 [%0];" :: "l"(pz + 128));
    }

    // ---- split all 512 centers ONCE (persistent for all tiles) -------------
    {
        const float4* ct = reinterpret_cast<const float4*>(cc);
        #pragma unroll 4
        for (int it = 0; it < 16; it++) {
            const int idx = it * 512 + tid;
            const int row = idx >> 4, c4 = idx & 15;
            const float4 v = ct[idx];
            float sq = v.x * v.x + v.y * v.y + v.z * v.z + v.w * v.w;
            sq += __shfl_xor_sync(~0u, sq, 1);
            sq += __shfl_xor_sync(~0u, sq, 2);
            sq += __shfl_xor_sync(~0u, sq, 4);
            sq += __shfl_xor_sync(~0u, sq, 8);
            if ((lane & 15) == 0) csq_s[row] = -sq * LOG2E;  // ready-to-add addend
            uint2 hi, lo;
            split2(v.x, v.y, hi.x, lo.x);
            split2(v.z, v.w, hi.y, lo.y);
            const uint32_t so = SWZ((uint32_t)(row * 128 + c4 * 8));
            *reinterpret_cast<uint2*>(smem + OFF_BHI + so) = hi;
            *reinterpret_cast<uint2*>(smem + OFF_BLO + so) = lo;
        }
    }

    // ---- lane decodes (m32 tile) -------------------------------------------
    const uint32_t aCol16 = ((lane >> 4) & 1) * 16;
    const uint32_t aRow0  = (uint32_t)(mt * 32 + ((lane >> 3) & 1) * 8 + (lane & 7));
    const uint32_t aoff0  = aRow0 * 128 + aCol16;
    const uint32_t aoff1  = (aRow0 + 16) * 128 + aCol16;
    const uint32_t bRowL  = ((lane >> 4) & 1) * 8 + (lane & 7);
    const uint32_t bK16   = ((lane >> 3) & 1) * 16;

    const int r0 = mt * 32 + (lane >> 2);   // r1=r0+8, r2=r0+16, r3=r0+24
    const uint32_t estg = sb + OFF_ESTG + (uint32_t)tid * 4;  // slot stride 2048

    float cta_loss = 0.f;

    // ======================= tile loop =====================================
    for (int tile = bid; tile < NTILES; tile += NCTAS) {

        // ---- split z tile: LDG (L2-hot from prefetch) -> A hi/lo -----------
        {
            const float SC = 2.0f * LOG2E;
            const float4* zt = z4 + (size_t)tile * 2048;
            #pragma unroll
            for (int it = 0; it < 4; it++) {
                const int idx = it * 512 + tid;
                const int row = idx >> 4, c4 = idx & 15;
                const float4 v = zt[idx];
                float sq = v.x * v.x + v.y * v.y + v.z * v.z + v.w * v.w;
                sq += __shfl_xor_sync(~0u, sq, 1);
                sq += __shfl_xor_sync(~0u, sq, 2);
                sq += __shfl_xor_sync(~0u, sq, 4);
                sq += __shfl_xor_sync(~0u, sq, 8);
                if ((lane & 15) == 0) zsq_s[row] = sq * LOG2E;   // zq' (log2)
                uint2 hi, lo;
                split2(SC * v.x, SC * v.y, hi.x, lo.x);
                split2(SC * v.z, SC * v.w, hi.y, lo.y);
                const uint32_t so = SWZ((uint32_t)(row * 128 + c4 * 8));
                *reinterpret_cast<uint2*>(smem + OFF_AHI + so) = hi;
                *reinterpret_cast<uint2*>(smem + OFF_ALO + so) = lo;
            }
        }
        __syncthreads();   // sync1: A/zsq visible (covers B on first tile)

        // ---- PASS 1: 2 chunks of 64 cols; 4 row streams; e -> hp/SMEM ------
        float m0, s0 = 0.f, t0 = 0.f;
        float m1, s1 = 0.f, t1 = 0.f;
        float m2, s2 = 0.f, t2 = 0.f;
        float m3, s3 = 0.f, t3 = 0.f;
        uint32_t hp[48];

        #pragma unroll
        for (int ci = 0; ci < 2; ci++) {
            const uint32_t chbase = (uint32_t)(grp * 128 + ci * 64);

            float acc[64];
            compute_chunk(acc, sb, chbase, aoff0, aoff1, bRowL, bK16);

            // u = cross' + (-csq'); chunk max per row stream
            float cm0 = -1e30f, cm1 = -1e30f, cm2 = -1e30f, cm3 = -1e30f;
            #pragma unroll
            for (int nt = 0; nt < 8; nt++) {
                const float2 cs = *reinterpret_cast<const float2*>(
                    csq_s + chbase + nt * 8 + (lane & 3) * 2);
                float* A = acc + nt * 4;
                float* B = acc + 32 + nt * 4;
                A[0] += cs.x;  A[1] += cs.y;   // r0
                A[2] += cs.x;  A[3] += cs.y;   // r1
                B[0] += cs.x;  B[1] += cs.y;   // r2
                B[2] += cs.x;  B[3] += cs.y;   // r3
                cm0 = fmaxf(cm0, fmaxf(A[0], A[1]));
                cm1 = fmaxf(cm1, fmaxf(A[2], A[3]));
                cm2 = fmaxf(cm2, fmaxf(B[0], B[1]));
                cm3 = fmaxf(cm3, fmaxf(B[2], B[3]));
            }
            cm0 = fmaxf(cm0, __shfl_xor_sync(~0u, cm0, 1));
            cm0 = fmaxf(cm0, __shfl_xor_sync(~0u, cm0, 2));
            cm1 = fmaxf(cm1, __shfl_xor_sync(~0u, cm1, 1));
            cm1 = fmaxf(cm1, __shfl_xor_sync(~0u, cm1, 2));
            cm2 = fmaxf(cm2, __shfl_xor_sync(~0u, cm2, 1));
            cm2 = fmaxf(cm2, __shfl_xor_sync(~0u, cm2, 2));
            cm3 = fmaxf(cm3, __shfl_xor_sync(~0u, cm3, 1));
            cm3 = fmaxf(cm3, __shfl_xor_sync(~0u, cm3, 2));
            if (ci == 0) {
                m0 = cm0; m1 = cm1; m2 = cm2; m3 = cm3;  // s=t=0, no rescale
            } else {
                const float nm0 = fmaxf(m0, cm0), f0 = ex2f(m0 - nm0);
                const float nm1 = fmaxf(m1, cm1), f1 = ex2f(m1 - nm1);
                const float nm2 = fmaxf(m2, cm2), f2 = ex2f(m2 - nm2);
                const float nm3 = fmaxf(m3, cm3), f3 = ex2f(m3 - nm3);
                s0 *= f0; t0 *= f0; m0 = nm0;
                s1 *= f1; t1 *= f1; m1 = nm1;
                s2 *= f2; t2 *= f2; m2 = nm2;
                s3 *= f3; t3 *= f3; m3 = nm3;
            }

            // ---- packed-f32x2 e-loop: chunk-local (sL, tL') accumulators ----
            // tL' = sum e*(u-m); fold back t += tL' + m*sL at chunk end.
            uint64_t sL0 = 0, sL1 = 0, sL2 = 0, sL3 = 0;
            uint64_t tL0 = 0, tL1 = 0, tL2 = 0, tL3 = 0;
            const uint64_t nmp0 = pk2(-m0, -m0);
            const uint64_t nmp1 = pk2(-m1, -m1);
            const uint64_t nmp2 = pk2(-m2, -m2);
            const uint64_t nmp3 = pk2(-m3, -m3);
            #pragma unroll
            for (int nt = 0; nt < 8; nt++) {
                float* A = acc + nt * 4;
                float* B = acc + 32 + nt * 4;
                const uint64_t u0 = add2(pk2(A[0], A[1]), nmp0);
                const uint64_t u1 = add2(pk2(A[2], A[3]), nmp1);
                const uint64_t u2 = add2(pk2(B[0], B[1]), nmp2);
                const uint64_t u3 = add2(pk2(B[2], B[3]), nmp3);
                float a0, b0, a1, b1, a2, b2, a3, b3;
                upk2(a0, b0, u0);  upk2(a1, b1, u1);
                upk2(a2, b2, u2);  upk2(a3, b3, u3);
                const float e00 = ex2f(a0), e01 = ex2f(b0);
                const float e10 = ex2f(a1), e11 = ex2f(b1);
                const float e20 = ex2f(a2), e21 = ex2f(b2);
                const float e30 = ex2f(a3), e31 = ex2f(b3);
                const uint64_t ep0 = pk2(e00, e01);
                const uint64_t ep1 = pk2(e10, e11);
                const uint64_t ep2 = pk2(e20, e21);
                const uint64_t ep3 = pk2(e30, e31);
                sL0 = add2(sL0, ep0);  tL0 = fma2(ep0, u0, tL0);
                sL1 = add2(sL1, ep1);  tL1 = fma2(ep1, u1, tL1);
                sL2 = add2(sL2, ep2);  tL2 = fma2(ep2, u2, tL2);
                sL3 = add2(sL3, ep3);  tL3 = fma2(ep3, u3, tL3);
                const __half2 h0 = __floats2half2_rn(e00, e01);
                const __half2 h1 = __floats2half2_rn(e10, e11);
                const __half2 h2 = __floats2half2_rn(e20, e21);
                const __half2 h3 = __floats2half2_rn(e30, e31);
                if (ci == 0) {
                    hp[nt]     = *reinterpret_cast<const uint32_t*>(&h0);
                    hp[8 + nt] = *reinterpret_cast<const uint32_t*>(&h1);
                    sts32(estg + (uint32_t)((nt * 2) * 2048),
                          *reinterpret_cast<const uint32_t*>(&h2));
                    sts32(estg + (uint32_t)((nt * 2 + 1) * 2048),
                          *reinterpret_cast<const uint32_t*>(&h3));
                } else {
                    hp[16 + nt] = *reinterpret_cast<const uint32_t*>(&h0);
                    hp[24 + nt] = *reinterpret_cast<const uint32_t*>(&h1);
                    hp[32 + nt] = *reinterpret_cast<const uint32_t*>(&h2);
                    hp[40 + nt] = *reinterpret_cast<const uint32_t*>(&h3);
                }
            }
            // fold chunk-local sums into running (m-corrected t)
            {
                float xa, xb, ya, yb;
                upk2(xa, xb, sL0); upk2(ya, yb, tL0);
                const float sl = xa + xb;
                s0 += sl;  t0 += ya + yb + m0 * sl;
                upk2(xa, xb, sL1); upk2(ya, yb, tL1);
                const float sl1v = xa + xb;
                s1 += sl1v;  t1 += ya + yb + m1 * sl1v;
                upk2(xa, xb, sL2); upk2(ya, yb, tL2);
                const float sl2v = xa + xb;
                s2 += sl2v;  t2 += ya + yb + m2 * sl2v;
                upk2(xa, xb, sL3); upk2(ya, yb, tL3);
                const float sl3v = xa + xb;
                s3 += sl3v;  t3 += ya + yb + m3 * sl3v;
            }
            if ((lane & 3) == 0) {
                const int ch = grp * 2 + ci;
                w_s[r0 * 9 + ch]        = m0;
                w_s[(r0 + 8) * 9 + ch]  = m1;
                w_s[(r0 + 16) * 9 + ch] = m2;
                w_s[(r0 + 24) * 9 + ch] = m3;
            }
        }

        // ---- group-local row reductions + publish (m, s, t_u) --------------
        s0 += __shfl_xor_sync(~0u, s0, 1);  s0 += __shfl_xor_sync(~0u, s0, 2);
        t0 += __shfl_xor_sync(~0u, t0, 1);  t0 += __shfl_xor_sync(~0u, t0, 2);
        s1 += __shfl_xor_sync(~0u, s1, 1);  s1 += __shfl_xor_sync(~0u, s1, 2);
        t1 += __shfl_xor_sync(~0u, t1, 1);  t1 += __shfl_xor_sync(~0u, t1, 2);
        s2 += __shfl_xor_sync(~0u, s2, 1);  s2 += __shfl_xor_sync(~0u, s2, 2);
        t2 += __shfl_xor_sync(~0u, t2, 1);  t2 += __shfl_xor_sync(~0u, t2, 2);
        s3 += __shfl_xor_sync(~0u, s3, 1);  s3 += __shfl_xor_sync(~0u, s3, 2);
        t3 += __shfl_xor_sync(~0u, t3, 1);  t3 += __shfl_xor_sync(~0u, t3, 2);
        if ((lane & 3) == 0) {
            float* p0 = mst_s + (size_t)(grp * 128 + r0) * 4;
            p0[0] = m0; p0[1] = s0; p0[2] = t0;
            float* p1 = mst_s + (size_t)(grp * 128 + r0 + 8) * 4;
            p1[0] = m1; p1[1] = s1; p1[2] = t1;
            float* p2 = mst_s + (size_t)(grp * 128 + r0 + 16) * 4;
            p2[0] = m2; p2[1] = s2; p2[2] = t2;
            float* p3 = mst_s + (size_t)(grp * 128 + r0 + 24) * 4;
            p3[0] = m3; p3[1] = s3; p3[2] = t3;
        }
        __syncthreads();   // sync2: mst published

        // ---- merge 4 groups per row (thread = row): Mv, inv, loss only -----
        float lossr = 0.f;
        if (tid < TM) {
            float Mv = -1e30f;
            float mg[4], sg[4], tg[4];
            #pragma unroll
            for (int g = 0; g < 4; g++) {
                const float* p = mst_s + (size_t)(g * 128 + tid) * 4;
                mg[g] = p[0]; sg[g] = p[1]; tg[g] = p[2];
                Mv = fmaxf(Mv, mg[g]);
            }
            float sF = 0.f, tF = 0.f;
            #pragma unroll
            for (int g = 0; g < 4; g++) {
                const float f = ex2f(mg[g] - Mv);
                sF += sg[g] * f; tF += tg[g] * f;
            }
            const float inv = 1.f / sF;
            lossr = (zsq_s[tid] - tF * inv) * LN2;
            mst_s[(size_t)tid * 4 + 3]         = Mv;    // pad slot of grp0 row
            mst_s[(size_t)(128 + tid) * 4 + 3] = inv;   // pad slot of grp1 row
        }
        #pragma unroll
        for (int o = 16; o; o >>= 1) lossr += __shfl_xor_sync(~0u, lossr, o);
        if (wid < 4 && lane == 0) red_s[wid] = lossr;
        __syncthreads();   // sync3: Mv/inv/red_s ready
        if (tid == 0)
            cta_loss += red_s[0] + red_s[1] + red_s[2] + red_s[3];

        // ---- L2-prefetch next z tile (overlaps pass 2) ---------------------
        {
            const int ntile = tile + NCTAS;
            if (ntile < NTILES) {
                const char* pz = reinterpret_cast<const char*>(
                    z4 + (size_t)ntile * 2048) + tid * 256;
                asm volatile("prefetch.global.L2 [%0];" :: "l"(pz));
                asm volatile("prefetch.global.L2 [%0];" :: "l"(pz + 128));
            }
        }

        // ---- PASS 2: q stores, packed e*w ----------------------------------
        {
            float* qt = q_out + (size_t)tile * TM * KC;
            const int c2 = (lane & 3) * 2;
            float Mvj[4], ivj[4];
            #pragma unroll
            for (int j = 0; j < 4; j++) {
                const int r = r0 + j * 8;
                Mvj[j] = mst_s[(size_t)r * 4 + 3];
                ivj[j] = mst_s[(size_t)(128 + r) * 4 + 3];
            }
            #pragma unroll
            for (int ci = 0; ci < 2; ci++) {
                const int ch = grp * 2 + ci;
                const int colb = grp * 128 + ci * 64 + c2;
                const float w0 = ex2f(w_s[r0 * 9 + ch]        - Mvj[0]) * ivj[0];
                const float w1 = ex2f(w_s[(r0 + 8) * 9 + ch]  - Mvj[1]) * ivj[1];
                const float w2 = ex2f(w_s[(r0 + 16) * 9 + ch] - Mvj[2]) * ivj[2];
                const float w3 = ex2f(w_s[(r0 + 24) * 9 + ch] - Mvj[3]) * ivj[3];
                const uint64_t wp0 = pk2(w0, w0);
                const uint64_t wp1 = pk2(w1, w1);
                const uint64_t wp2 = pk2(w2, w2);
                const uint64_t wp3 = pk2(w3, w3);
                #pragma unroll
                for (int nt = 0; nt < 8; nt++) {
                    uint32_t u0, u1, u2, u3;
                    if (ci == 0) {
                        u0 = hp[nt];  u1 = hp[8 + nt];
                        u2 = lds32(estg + (uint32_t)((nt * 2) * 2048));
                        u3 = lds32(estg + (uint32_t)((nt * 2 + 1) * 2048));
                    } else {
                        u0 = hp[16 + nt]; u1 = hp[24 + nt];
                        u2 = hp[32 + nt]; u3 = hp[40 + nt];
                    }
                    const float2 e0 = __half22float2(*reinterpret_cast<const __half2*>(&u0));
                    const float2 e1 = __half22float2(*reinterpret_cast<const __half2*>(&u1));
                    const float2 e2 = __half22float2(*reinterpret_cast<const __half2*>(&u2));
                    const float2 e3 = __half22float2(*reinterpret_cast<const __half2*>(&u3));
                    const uint64_t o0 = mul2(pk2(e0.x, e0.y), wp0);
                    const uint64_t o1 = mul2(pk2(e1.x, e1.y), wp1);
                    const uint64_t o2 = mul2(pk2(e2.x, e2.y), wp2);
                    const uint64_t o3 = mul2(pk2(e3.x, e3.y), wp3);
                    *reinterpret_cast<uint64_t*>(qt + (size_t)r0 * KC + colb + nt * 8) = o0;
                    *reinterpret_cast<uint64_t*>(qt + (size_t)(r0 + 8) * KC + colb + nt * 8) = o1;
                    *reinterpret_cast<uint64_t*>(qt + (size_t)(r0 + 16) * KC + colb + nt * 8) = o2;
                    *reinterpret_cast<uint64_t*>(qt + (size_t)(r0 + 24) * KC + colb + nt * 8) = o3;
                }
            }
        }
    } // tile loop

    if (tid == 0) g_loss_partial[bid] = cta_loss;

    // ---- last-CTA loss finalize (deterministic fixed-order sum) ------------
    __threadfence();
    if (tid == 0) {
        const unsigned int old = atomicAdd(&g_done, 1u);
        *flag_s = (old == (unsigned int)(NCTAS - 1)) ? 1u : 0u;
    }
    __syncthreads();
    if (*flag_s) {
        double a = (tid < NCTAS) ? (double)g_loss_partial[tid] : 0.0;
        #pragma unroll
        for (int o = 16; o; o >>= 1) a += __shfl_xor_sync(~0u, a, o);
        double* dred = reinterpret_cast<double*>(smem + OFF_RED + 128);
        if (lane == 0) dred[wid] = a;
        __syncthreads();
        if (tid == 0) {
            double t = 0.0;
            #pragma unroll
            for (int i = 0; i < 16; i++) t += dred[i];
            if (loss_out) *loss_out = (float)(t / (double)B_ROWS);
            g_done = 0;   // reset for next graph replay
        }
    }
}

// ============================================================================
// Launch
// ============================================================================
extern "C" void kernel_launch(void* const* d_in, const int* in_sizes, int n_in,
                              void* d_out, int out_size) {
    const float* z  = (const float*)d_in[0];
    const float* cc = (const float*)d_in[1];
    float* q = (float*)d_out;

    const long long q_elems = (long long)B_ROWS * KC;  // 67108864
    float* loss_out = ((long long)out_size > q_elems) ? (q + q_elems) : nullptr;

    cudaFuncSetAttribute(soft_kmeans_kernel,
                         cudaFuncAttributeMaxDynamicSharedMemorySize, SMEM_BYTES);
    soft_kmeans_kernel<<<NCTAS, 512, SMEM_BYTES>>>(z, cc, q, loss_out);
}